// round 2
// baseline (speedup 1.0000x reference)
#include <cuda_runtime.h>

// ---------------------------------------------------------------------------
// Problem constants
//   B=8, C_IN=256, DIM=64, HEADS=8, D_IN=128, DKQ=8, DV=16, QKV=32
//   N = B*DIM*DIM = 32768 "pixels"
// ---------------------------------------------------------------------------
#define NT 32768
#define EPSV 1e-5f

// Scratch (module-load allocated; no runtime allocs)
__device__ float  g_y1[128 * NT];      // conv-in raw output, layout [c][b][w][h]
__device__ float  g_qkv[256 * NT];     // qkv, layout [o][bw][pos]
__device__ float  g_outatt[256 * NT];  // attention out (sve ch 0..127, sv 128..255)
__device__ float  g_x3[128 * NT];      // att combined (also reused as x4)
__device__ float  g_y2[256 * NT];      // conv-out raw output [o][n1]
// stats: groups [sum C][sq C]:
//  convin @0(256) att1 @256(48) out1 @304(512) att2 @816(48) out2 @864(512) convout @1376(512)
__device__ double g_st[1888];
__device__ float  g_sb[1888];          // same offsets: [scale C][bias C]

__global__ void zero_stats() {
    int i = blockIdx.x * 256 + threadIdx.x;
    if (i < 1888) g_st[i] = 0.0;
}

__global__ void make_scale(int stoff, const float* __restrict__ gamma,
                           const float* __restrict__ beta, int sboff, int C, float invN) {
    int t = blockIdx.x * 64 + threadIdx.x;
    if (t >= C) return;
    double mean = g_st[stoff + t] * (double)invN;
    double var  = g_st[stoff + C + t] * (double)invN - mean * mean;
    float s = gamma[t] * rsqrtf((float)var + EPSV);
    g_sb[sboff + t]     = s;
    g_sb[sboff + C + t] = beta[t] - (float)mean * s;
}

// ---------------------------------------------------------------------------
// GEMM: C[MxNT] = A[MxK] * B[KxNT]
// MODE 0: conv-in  : B = x_in gather [b][c][hw], epilogue scatter to y1[c][b][w][h] + stats
// MODE 1: qkv1     : B = g_y1 with BN(scale/bias from convin group)+relu prologue -> g_qkv
// MODE 2: qkv2     : B = g_x3 plain -> g_qkv
// MODE 3: conv-out : B = g_x3 plain -> g_y2 + stats
// ---------------------------------------------------------------------------
template <int MODE>
__global__ void __launch_bounds__(256) gemm_k(const float* __restrict__ A,
                                              const float* __restrict__ Bext, int K) {
    __shared__ float As[32][128];
    __shared__ float Bs[32][128];
    __shared__ float ssum[128], ssq[128];
    const int n0 = blockIdx.x * 128;
    const int m0 = blockIdx.y * 128;
    const int tid = threadIdx.x;
    const int ty = tid >> 4, tx = tid & 15;

    const float* Bp = (MODE == 0) ? Bext : ((MODE == 1) ? g_y1 : g_x3);
    float* Cp = (MODE == 0) ? g_y1 : ((MODE == 3) ? g_y2 : g_qkv);

    float acc[8][8];
#pragma unroll
    for (int i = 0; i < 8; i++)
#pragma unroll
        for (int j = 0; j < 8; j++) acc[i][j] = 0.f;

    for (int k0 = 0; k0 < K; k0 += 32) {
#pragma unroll
        for (int r = 0; r < 4; r++) {
            int t = tid + r * 256;
            int row = t >> 3, c4 = (t & 7) * 4;
            float4 v = *(const float4*)&A[(m0 + row) * K + k0 + c4];
            As[c4 + 0][row] = v.x; As[c4 + 1][row] = v.y;
            As[c4 + 2][row] = v.z; As[c4 + 3][row] = v.w;
        }
#pragma unroll
        for (int r = 0; r < 4; r++) {
            int t = tid + r * 256;
            int kr = t >> 5, m4 = (t & 31) * 4;
            float4 v;
            if (MODE == 0) {
                // x_in[b][c][hw]; column m = b*4096 + hw, block stays within one b
                v = *(const float4*)&Bp[(n0 >> 12) * 1048576 + (k0 + kr) * 4096 + (n0 & 4095) + m4];
            } else {
                v = *(const float4*)&Bp[(k0 + kr) * NT + n0 + m4];
                if (MODE == 1) {
                    float s = g_sb[k0 + kr], bi = g_sb[128 + k0 + kr];
                    v.x = fmaxf(fmaf(v.x, s, bi), 0.f);
                    v.y = fmaxf(fmaf(v.y, s, bi), 0.f);
                    v.z = fmaxf(fmaf(v.z, s, bi), 0.f);
                    v.w = fmaxf(fmaf(v.w, s, bi), 0.f);
                }
            }
            *(float4*)&Bs[kr][m4] = v;
        }
        __syncthreads();
#pragma unroll
        for (int kk = 0; kk < 32; kk++) {
            float a[8], b[8];
            *(float4*)&a[0] = *(const float4*)&As[kk][ty * 8];
            *(float4*)&a[4] = *(const float4*)&As[kk][ty * 8 + 4];
            *(float4*)&b[0] = *(const float4*)&Bs[kk][tx * 8];
            *(float4*)&b[4] = *(const float4*)&Bs[kk][tx * 8 + 4];
#pragma unroll
            for (int i = 0; i < 8; i++)
#pragma unroll
                for (int j = 0; j < 8; j++) acc[i][j] = fmaf(a[i], b[j], acc[i][j]);
        }
        __syncthreads();
    }

    if (MODE == 0 || MODE == 3) {
        for (int t = tid; t < 128; t += 256) { ssum[t] = 0.f; ssq[t] = 0.f; }
        __syncthreads();
    }

    if (MODE == 0) {
        const int bb = n0 >> 12, hw0 = n0 & 4095;
#pragma unroll
        for (int i = 0; i < 8; i++) {
            int o = ty * 8 + i;  // m0 == 0 (M=128)
            float rs = 0.f, rq = 0.f;
#pragma unroll
            for (int j = 0; j < 8; j++) {
                int hw = hw0 + tx * 8 + j;  // hw = h*64 + w
                float v = acc[i][j];
                Cp[o * NT + bb * 4096 + (hw & 63) * 64 + (hw >> 6)] = v;  // [c][b][w][h]
                rs += v; rq += v * v;
            }
            atomicAdd(&ssum[o], rs);
            atomicAdd(&ssq[o], rq);
        }
    } else {
#pragma unroll
        for (int i = 0; i < 8; i++) {
            int o = m0 + ty * 8 + i;
            float4 v0 = make_float4(acc[i][0], acc[i][1], acc[i][2], acc[i][3]);
            float4 v1 = make_float4(acc[i][4], acc[i][5], acc[i][6], acc[i][7]);
            *(float4*)&Cp[o * NT + n0 + tx * 8] = v0;
            *(float4*)&Cp[o * NT + n0 + tx * 8 + 4] = v1;
            if (MODE == 3) {
                float rs = 0.f, rq = 0.f;
#pragma unroll
                for (int j = 0; j < 8; j++) { rs += acc[i][j]; rq += acc[i][j] * acc[i][j]; }
                atomicAdd(&ssum[ty * 8 + i], rs);
                atomicAdd(&ssq[ty * 8 + i], rq);
            }
        }
    }

    if (MODE == 0 || MODE == 3) {
        __syncthreads();
        const int base = (MODE == 0) ? 0 : 1376;
        const int Csz  = (MODE == 0) ? 128 : 256;
        if (tid < 128) {
            atomicAdd(&g_st[base + m0 + tid], (double)ssum[tid]);
            atomicAdd(&g_st[base + Csz + m0 + tid], (double)ssq[tid]);
        }
    }
}

// ---------------------------------------------------------------------------
// Attention pass 1: per (bw, head) compute qr/kr/dots and accumulate
// per-channel (head*3 + t) sum / sumsq for the cat-BN.
// ---------------------------------------------------------------------------
__global__ void __launch_bounds__(256) att_pass1(const float* __restrict__ rel, int stoff) {
    const int bw = blockIdx.x, h = blockIdx.y, tid = threadIdx.x;
    __shared__ float sq[8][65], sk[8][65];
    __shared__ float srel[16][129];
    __shared__ float red[8][6];

#pragma unroll
    for (int r = 0; r < 4; r++) {
        int t = tid + r * 256;  // 16*64
        int qi = t >> 6, d = t & 63;
        float v = g_qkv[(qi * 8 + h) * NT + bw * 64 + d];
        if (qi < 8) sq[qi][d] = v; else sk[qi - 8][d] = v;
    }
    for (int t = tid; t < 16 * 127; t += 256) srel[t / 127][t % 127] = rel[t];
    __syncthreads();

    const int d = tid >> 2, jb = (tid & 3) * 16;
    float qd[8], kd[8];
#pragma unroll
    for (int i = 0; i < 8; i++) { qd[i] = sq[i][d]; kd[i] = sk[i][d]; }
    float s1 = 0, q1 = 0, s2 = 0, q2 = 0, s3 = 0, q3 = 0;
    for (int jj = 0; jj < 16; jj++) {
        int j = jb + jj, idx = d - j + 63;
        float qr = 0, kr = 0, dt = 0;
#pragma unroll
        for (int i = 0; i < 8; i++) {
            qr = fmaf(qd[i], srel[i][idx], qr);
            kr = fmaf(kd[i], srel[8 + i][idx], kr);
            dt = fmaf(qd[i], sk[i][j], dt);
        }
        s1 += qr; q1 += qr * qr;
        s2 += kr; q2 += kr * kr;
        s3 += dt; q3 += dt * dt;
    }
#pragma unroll
    for (int off = 16; off > 0; off >>= 1) {
        s1 += __shfl_xor_sync(~0u, s1, off); q1 += __shfl_xor_sync(~0u, q1, off);
        s2 += __shfl_xor_sync(~0u, s2, off); q2 += __shfl_xor_sync(~0u, q2, off);
        s3 += __shfl_xor_sync(~0u, s3, off); q3 += __shfl_xor_sync(~0u, q3, off);
    }
    int wid = tid >> 5;
    if ((tid & 31) == 0) {
        red[wid][0] = s1; red[wid][1] = q1; red[wid][2] = s2;
        red[wid][3] = q2; red[wid][4] = s3; red[wid][5] = q3;
    }
    __syncthreads();
    if (tid < 6) {
        float a = 0.f;
#pragma unroll
        for (int w = 0; w < 8; w++) a += red[w][tid];
        int t = tid >> 1;     // 0:qr 1:kr 2:dots
        int isq = tid & 1;
        atomicAdd(&g_st[stoff + isq * 24 + h * 3 + t], (double)a);
    }
}

// ---------------------------------------------------------------------------
// Attention pass 2: recompute logits with BN applied, softmax, sv & sve,
// write outputs + accumulate per-channel stats for the out-BN (256 ch).
// ---------------------------------------------------------------------------
__global__ void __launch_bounds__(256) att_pass2(const float* __restrict__ rel, int sba, int sto) {
    const int bw = blockIdx.x, h = blockIdx.y, tid = threadIdx.x;
    __shared__ float sq[8][65], sk[8][65], svv[16][65];
    __shared__ float srel[32][129];
    __shared__ float sat[64][65];

#pragma unroll
    for (int r = 0; r < 8; r++) {
        int t = tid + r * 256;  // 32*64
        int qi = t >> 6, d = t & 63;
        float v = g_qkv[(qi * 8 + h) * NT + bw * 64 + d];
        if (qi < 8) sq[qi][d] = v;
        else if (qi < 16) sk[qi - 8][d] = v;
        else svv[qi - 16][d] = v;
    }
    for (int t = tid; t < 32 * 127; t += 256) srel[t / 127][t % 127] = rel[t];
    const float s0 = g_sb[sba + h * 3], s1v = g_sb[sba + h * 3 + 1], s2v = g_sb[sba + h * 3 + 2];
    const float bsum = g_sb[sba + 24 + h * 3] + g_sb[sba + 24 + h * 3 + 1] + g_sb[sba + 24 + h * 3 + 2];
    __syncthreads();

    {   // logits + softmax (4 lanes per row d)
        const int d = tid >> 2, jb = (tid & 3) * 16;
        float qd[8], kd[8];
#pragma unroll
        for (int i = 0; i < 8; i++) { qd[i] = sq[i][d]; kd[i] = sk[i][d]; }
        float lv[16], mx = -3.4e38f;
        for (int jj = 0; jj < 16; jj++) {
            int j = jb + jj, idx = d - j + 63;
            float qr = 0, kr = 0, dt = 0;
#pragma unroll
            for (int i = 0; i < 8; i++) {
                qr = fmaf(qd[i], srel[i][idx], qr);
                kr = fmaf(kd[i], srel[8 + i][idx], kr);
                dt = fmaf(qd[i], sk[i][j], dt);
            }
            float l = qr * s0 + kr * s1v + dt * s2v + bsum;
            lv[jj] = l;
            mx = fmaxf(mx, l);
        }
        mx = fmaxf(mx, __shfl_xor_sync(~0u, mx, 1));
        mx = fmaxf(mx, __shfl_xor_sync(~0u, mx, 2));
        float se = 0.f;
#pragma unroll
        for (int jj = 0; jj < 16; jj++) { float e = __expf(lv[jj] - mx); lv[jj] = e; se += e; }
        se += __shfl_xor_sync(~0u, se, 1);
        se += __shfl_xor_sync(~0u, se, 2);
        float inv = 1.f / se;
#pragma unroll
        for (int jj = 0; jj < 16; jj++) sat[d][jb + jj] = lv[jj] * inv;
    }
    __syncthreads();

    {   // sv[i][d] and sve[i][d]; thread: i = tid/16, d lanes = tid%16 (+16r)
        const int i = tid >> 4, dl = tid & 15;
        float se_s = 0, se_q = 0, sv_s = 0, sv_q = 0;
        const float* relv = &srel[16 + i][0];
        for (int r = 0; r < 4; r++) {
            int dd = dl + 16 * r;
            float av = 0.f, ae = 0.f;
#pragma unroll
            for (int j = 0; j < 64; j++) {
                float a = sat[dd][j];
                av = fmaf(a, svv[i][j], av);
                ae = fmaf(a, relv[dd - j + 63], ae);
            }
            g_outatt[(h * 16 + i) * NT + bw * 64 + dd] = ae;
            g_outatt[(128 + h * 16 + i) * NT + bw * 64 + dd] = av;
            se_s += ae; se_q += ae * ae;
            sv_s += av; sv_q += av * av;
        }
#pragma unroll
        for (int off = 1; off < 16; off <<= 1) {
            se_s += __shfl_xor_sync(~0u, se_s, off); se_q += __shfl_xor_sync(~0u, se_q, off);
            sv_s += __shfl_xor_sync(~0u, sv_s, off); sv_q += __shfl_xor_sync(~0u, sv_q, off);
        }
        if (dl == 0) {
            int ch = h * 16 + i;
            atomicAdd(&g_st[sto + ch], (double)se_s);
            atomicAdd(&g_st[sto + 256 + ch], (double)se_q);
            atomicAdd(&g_st[sto + 128 + ch], (double)sv_s);
            atomicAdd(&g_st[sto + 256 + 128 + ch], (double)sv_q);
        }
    }
}

// combine att1: x3[c][b][h][w] = bn(sve) + bn(sv), with h<->w transpose
__global__ void __launch_bounds__(256) combine1() {
    const int c = blockIdx.x, b = blockIdx.y, tid = threadIdx.x;
    __shared__ float tile[64][65];
    const float sA = g_sb[304 + c],        bA = g_sb[304 + 256 + c];
    const float sB = g_sb[304 + c + 128],  bB = g_sb[304 + 256 + c + 128];
    const float* pA = g_outatt + c * NT + b * 4096;          // [(w)*64 + h]
    const float* pB = g_outatt + (c + 128) * NT + b * 4096;
    for (int t = tid; t < 4096; t += 256)
        tile[t >> 6][t & 63] = pA[t] * sA + bA + pB[t] * sB + bB;
    __syncthreads();
    float* q = g_x3 + c * NT + b * 4096;                     // [(h)*64 + w]
    for (int t = tid; t < 4096; t += 256)
        q[t] = tile[t & 63][t >> 6];
}

// combine att2: x4 = relu(bn(sve2) + bn(sv2)), no transpose needed
__global__ void __launch_bounds__(256) combine2() {
    int idx = blockIdx.x * 256 + threadIdx.x;  // 128*NT
    int c = idx >> 15, m = idx & (NT - 1);
    float v = g_outatt[c * NT + m] * g_sb[864 + c] + g_sb[864 + 256 + c]
            + g_outatt[(c + 128) * NT + m] * g_sb[864 + c + 128] + g_sb[864 + 256 + c + 128];
    g_x3[idx] = fmaxf(v, 0.f);
}

// final: out = relu(bn(conv_out) + x_in)
__global__ void __launch_bounds__(256) final_k(const float* __restrict__ x_in,
                                               float* __restrict__ out) {
    int idx = blockIdx.x * 256 + threadIdx.x;  // 256*NT
    int o = idx >> 15, m = idx & (NT - 1);
    int b = m >> 12, hw = m & 4095;
    float v = g_y2[idx] * g_sb[1376 + o] + g_sb[1376 + 256 + o];
    int oidx = (b * 256 + o) * 4096 + hw;
    v += x_in[oidx];
    out[oidx] = fmaxf(v, 0.f);
}

// ---------------------------------------------------------------------------
extern "C" void kernel_launch(void* const* d_in, const int* in_sizes, int n_in,
                              void* d_out, int out_size) {
    (void)in_sizes; (void)n_in; (void)out_size;
    const float* x_in   = (const float*)d_in[0];
    const float* w_in   = (const float*)d_in[1];
    const float* g_in   = (const float*)d_in[2];
    const float* b_in   = (const float*)d_in[3];
    const float* w_out  = (const float*)d_in[4];
    const float* g_out  = (const float*)d_in[5];
    const float* b_out  = (const float*)d_in[6];
    const float* wqkv_h = (const float*)d_in[7];
    const float* rel_h  = (const float*)d_in[8];
    const float* ga_h   = (const float*)d_in[9];
    const float* ba_h   = (const float*)d_in[10];
    const float* go_h   = (const float*)d_in[11];
    const float* bo_h   = (const float*)d_in[12];
    const float* wqkv_w = (const float*)d_in[13];
    const float* rel_w  = (const float*)d_in[14];
    const float* ga_w   = (const float*)d_in[15];
    const float* ba_w   = (const float*)d_in[16];
    const float* go_w   = (const float*)d_in[17];
    const float* bo_w   = (const float*)d_in[18];

    zero_stats<<<8, 256>>>();

    // conv-in (+stats) -> y1
    gemm_k<0><<<dim3(256, 1), 256>>>(w_in, x_in, 256);
    make_scale<<<2, 64>>>(0, g_in, b_in, 0, 128, 1.f / 32768.f);

    // --- axial attention along H ---
    gemm_k<1><<<dim3(256, 2), 256>>>(wqkv_h, nullptr, 128);      // BN+relu prologue
    att_pass1<<<dim3(512, 8), 256>>>(rel_h, 256);
    make_scale<<<1, 64>>>(256, ga_h, ba_h, 256, 24, 1.f / 2097152.f);
    att_pass2<<<dim3(512, 8), 256>>>(rel_h, 256, 304);
    make_scale<<<4, 64>>>(304, go_h, bo_h, 304, 256, 1.f / 32768.f);
    combine1<<<dim3(128, 8), 256>>>();                           // bn-sum + transpose -> x3

    // --- axial attention along W ---
    gemm_k<2><<<dim3(256, 2), 256>>>(wqkv_w, nullptr, 128);
    att_pass1<<<dim3(512, 8), 256>>>(rel_w, 816);
    make_scale<<<1, 64>>>(816, ga_w, ba_w, 816, 24, 1.f / 2097152.f);
    att_pass2<<<dim3(512, 8), 256>>>(rel_w, 816, 864);
    make_scale<<<4, 64>>>(864, go_w, bo_w, 864, 256, 1.f / 32768.f);
    combine2<<<16384, 256>>>();                                  // bn-sum + relu -> x4

    // conv-out (+stats) -> y2
    gemm_k<3><<<dim3(256, 2), 256>>>(w_out, nullptr, 128);
    make_scale<<<4, 64>>>(1376, g_out, b_out, 1376, 256, 1.f / 32768.f);

    final_k<<<32768, 256>>>(x_in, (float*)d_out);
}

// round 3
// speedup vs baseline: 1.0658x; 1.0658x over previous
#include <cuda_runtime.h>

// ---------------------------------------------------------------------------
// Problem constants
//   B=8, C_IN=256, DIM=64, HEADS=8, D_IN=128, DKQ=8, DV=16, QKV=32
//   N = B*DIM*DIM = 32768 "pixels"; sequences: 512 of length 64
// ---------------------------------------------------------------------------
#define NT 32768
#define EPSV 1e-5f

__device__ float  g_y1[128 * NT];      // conv-in raw output, layout [c][b][w][h]
__device__ float  g_qkv[256 * NT];     // qkv, layout [o][bw][pos]
__device__ float  g_outatt[256 * NT];  // attention out (sve ch 0..127, sv 128..255)
__device__ float  g_x3[128 * NT];      // att combined (also reused as x4)
__device__ float  g_y2[256 * NT];      // conv-out raw output [o][n1]
// stats offsets: convin @0(256) att1 @256(48) out1 @304(512) att2 @816(48)
//                out2 @864(512) convout @1376(512)
__device__ double g_st[1888];
__device__ float  g_sb[1888];

// Precomputed rel-embedding tables (per direction, overwritten between dirs)
__device__ float g_Tq[8 * 64], g_Tk[8 * 64];
__device__ float g_Sq[36 * 64], g_Sk[36 * 64];

__device__ const int c_pi[36] = {0,0,0,0,0,0,0,0, 1,1,1,1,1,1,1, 2,2,2,2,2,2,
                                 3,3,3,3,3, 4,4,4,4, 5,5,5, 6,6, 7};
__device__ const int c_pj[36] = {0,1,2,3,4,5,6,7, 1,2,3,4,5,6,7, 2,3,4,5,6,7,
                                 3,4,5,6,7, 4,5,6,7, 5,6,7, 6,7, 7};

__global__ void zero_stats() {
    int i = blockIdx.x * 256 + threadIdx.x;
    if (i < 1888) g_st[i] = 0.0;
}

__global__ void make_scale(int stoff, const float* __restrict__ gamma,
                           const float* __restrict__ beta, int sboff, int C, float invN) {
    int t = blockIdx.x * 64 + threadIdx.x;
    if (t >= C) return;
    double mean = g_st[stoff + t] * (double)invN;
    double var  = g_st[stoff + C + t] * (double)invN - mean * mean;
    float s = gamma[t] * rsqrtf((float)var + EPSV);
    g_sb[sboff + t]     = s;
    g_sb[sboff + C + t] = beta[t] - (float)mean * s;
}

// ---------------------------------------------------------------------------
// GEMM: C[MxNT] = A[MxK] * B[KxNT]  (MODE 0 conv-in, 1 qkv w/ BN+relu prologue,
// 2 qkv plain, 3 conv-out)
// ---------------------------------------------------------------------------
template <int MODE>
__global__ void __launch_bounds__(256) gemm_k(const float* __restrict__ A,
                                              const float* __restrict__ Bext, int K) {
    __shared__ float As[32][128];
    __shared__ float Bs[32][128];
    __shared__ float ssum[128], ssq[128];
    const int n0 = blockIdx.x * 128;
    const int m0 = blockIdx.y * 128;
    const int tid = threadIdx.x;
    const int ty = tid >> 4, tx = tid & 15;

    const float* Bp = (MODE == 0) ? Bext : ((MODE == 1) ? g_y1 : g_x3);
    float* Cp = (MODE == 0) ? g_y1 : ((MODE == 3) ? g_y2 : g_qkv);

    float acc[8][8];
#pragma unroll
    for (int i = 0; i < 8; i++)
#pragma unroll
        for (int j = 0; j < 8; j++) acc[i][j] = 0.f;

    for (int k0 = 0; k0 < K; k0 += 32) {
#pragma unroll
        for (int r = 0; r < 4; r++) {
            int t = tid + r * 256;
            int row = t >> 3, c4 = (t & 7) * 4;
            float4 v = *(const float4*)&A[(m0 + row) * K + k0 + c4];
            As[c4 + 0][row] = v.x; As[c4 + 1][row] = v.y;
            As[c4 + 2][row] = v.z; As[c4 + 3][row] = v.w;
        }
#pragma unroll
        for (int r = 0; r < 4; r++) {
            int t = tid + r * 256;
            int kr = t >> 5, m4 = (t & 31) * 4;
            float4 v;
            if (MODE == 0) {
                v = *(const float4*)&Bp[(n0 >> 12) * 1048576 + (k0 + kr) * 4096 + (n0 & 4095) + m4];
            } else {
                v = *(const float4*)&Bp[(k0 + kr) * NT + n0 + m4];
                if (MODE == 1) {
                    float s = g_sb[k0 + kr], bi = g_sb[128 + k0 + kr];
                    v.x = fmaxf(fmaf(v.x, s, bi), 0.f);
                    v.y = fmaxf(fmaf(v.y, s, bi), 0.f);
                    v.z = fmaxf(fmaf(v.z, s, bi), 0.f);
                    v.w = fmaxf(fmaf(v.w, s, bi), 0.f);
                }
            }
            *(float4*)&Bs[kr][m4] = v;
        }
        __syncthreads();
#pragma unroll
        for (int kk = 0; kk < 32; kk++) {
            float a[8], b[8];
            *(float4*)&a[0] = *(const float4*)&As[kk][ty * 8];
            *(float4*)&a[4] = *(const float4*)&As[kk][ty * 8 + 4];
            *(float4*)&b[0] = *(const float4*)&Bs[kk][tx * 8];
            *(float4*)&b[4] = *(const float4*)&Bs[kk][tx * 8 + 4];
#pragma unroll
            for (int i = 0; i < 8; i++)
#pragma unroll
                for (int j = 0; j < 8; j++) acc[i][j] = fmaf(a[i], b[j], acc[i][j]);
        }
        __syncthreads();
    }

    if (MODE == 0 || MODE == 3) {
        for (int t = tid; t < 128; t += 256) { ssum[t] = 0.f; ssq[t] = 0.f; }
        __syncthreads();
    }

    if (MODE == 0) {
        const int bb = n0 >> 12, hw0 = n0 & 4095;
#pragma unroll
        for (int i = 0; i < 8; i++) {
            int o = ty * 8 + i;
            float rs = 0.f, rq = 0.f;
#pragma unroll
            for (int j = 0; j < 8; j++) {
                int hw = hw0 + tx * 8 + j;
                float v = acc[i][j];
                Cp[o * NT + bb * 4096 + (hw & 63) * 64 + (hw >> 6)] = v;
                rs += v; rq += v * v;
            }
            atomicAdd(&ssum[o], rs);
            atomicAdd(&ssq[o], rq);
        }
    } else {
#pragma unroll
        for (int i = 0; i < 8; i++) {
            int o = m0 + ty * 8 + i;
            float4 v0 = make_float4(acc[i][0], acc[i][1], acc[i][2], acc[i][3]);
            float4 v1 = make_float4(acc[i][4], acc[i][5], acc[i][6], acc[i][7]);
            *(float4*)&Cp[o * NT + n0 + tx * 8] = v0;
            *(float4*)&Cp[o * NT + n0 + tx * 8 + 4] = v1;
            if (MODE == 3) {
                float rs = 0.f, rq = 0.f;
#pragma unroll
                for (int j = 0; j < 8; j++) { rs += acc[i][j]; rq += acc[i][j] * acc[i][j]; }
                atomicAdd(&ssum[ty * 8 + i], rs);
                atomicAdd(&ssq[ty * 8 + i], rq);
            }
        }
    }

    if (MODE == 0 || MODE == 3) {
        __syncthreads();
        const int base = (MODE == 0) ? 0 : 1376;
        const int Csz  = (MODE == 0) ? 128 : 256;
        if (tid < 128) {
            atomicAdd(&g_st[base + m0 + tid], (double)ssum[tid]);
            atomicAdd(&g_st[base + Csz + m0 + tid], (double)ssq[tid]);
        }
    }
}

// ---------------------------------------------------------------------------
// prep_S: precompute sliding-window tables of the rel embedding.
//   T*[i][d]    = sum_{u=d}^{d+63} R_i[u]
//   S*[p][d]    = sum_{u=d}^{d+63} R_i[u]*R_i'[u]   (p enumerates i<=i' pairs)
// q uses rel rows 0..7, k uses rows 8..15.
// ---------------------------------------------------------------------------
__global__ void __launch_bounds__(256) prep_S(const float* __restrict__ rel) {
    __shared__ float r[16][127];
    for (int t = threadIdx.x; t < 16 * 127; t += 256) r[t / 127][t % 127] = rel[t];
    __syncthreads();
    for (int t = threadIdx.x; t < 1024; t += 256) {
        int which = t >> 9, i = (t >> 6) & 7, d = t & 63;
        const float* rr = r[which * 8 + i];
        float s = 0.f;
        for (int u = 0; u < 64; u++) s += rr[d + u];
        (which ? g_Tk : g_Tq)[i * 64 + d] = s;
    }
    for (int t = threadIdx.x; t < 4608; t += 256) {
        int which = t / 2304, rem = t % 2304, p = rem >> 6, d = rem & 63;
        const float* a = r[which * 8 + c_pi[p]];
        const float* b = r[which * 8 + c_pj[p]];
        float s = 0.f;
        for (int u = 0; u < 64; u++) s = fmaf(a[d + u], b[d + u], s);
        (which ? g_Sk : g_Sq)[p * 64 + d] = s;
    }
}

// ---------------------------------------------------------------------------
// att_stats: BN statistics of qr/kr/dots WITHOUT materializing logits.
//   sum  dots = sum_i (sum_d q)(sum_j k)
//   sum  dots^2 = sum_{ii'} Gq[ii'] Gk[ii']       (Gram matrices)
//   sum  qr   = sum_i sum_d q_id Tq[i][d]
//   sum  qr^2 = sum_d sum_{ii'} q_id q_i'd Sq[ii'][d]   (kr analogous with k)
// One block per sequence bw (512), warp w handles head w.
// ---------------------------------------------------------------------------
__global__ void __launch_bounds__(256) att_stats(int stoff) {
    const int bw = blockIdx.x, tid = threadIdx.x;
    __shared__ float qT[8][512];   // [h][d*8 + i]
    __shared__ float kT[8][512];
    __shared__ float rsq[8][8], rsk[8][8], tqs[8][8], tks[8][8];

    for (int t = tid; t < 8192; t += 256) {
        int which = t >> 12, o = (t >> 6) & 63, d = t & 63;
        float v = g_qkv[(which * 64 + o) * NT + bw * 64 + d];
        int h = o & 7, i = o >> 3;
        if (which == 0) qT[h][d * 8 + i] = v; else kT[h][d * 8 + i] = v;
    }
    __syncthreads();

    const int h = tid >> 5, lane = tid & 31;
    if (lane < 8) {
        float s = 0.f;
        for (int d = 0; d < 64; d++) s += qT[h][d * 8 + lane];
        rsq[h][lane] = s;
    } else if (lane < 16) {
        int i = lane - 8; float s = 0.f;
        for (int d = 0; d < 64; d++) s += kT[h][d * 8 + i];
        rsk[h][i] = s;
    } else if (lane < 24) {
        int i = lane - 16; float s = 0.f;
        for (int d = 0; d < 64; d++) s = fmaf(qT[h][d * 8 + i], __ldg(&g_Tq[i * 64 + d]), s);
        tqs[h][i] = s;
    } else {
        int i = lane - 24; float s = 0.f;
        for (int d = 0; d < 64; d++) s = fmaf(kT[h][d * 8 + i], __ldg(&g_Tk[i * 64 + d]), s);
        tks[h][i] = s;
    }

    float dsq = 0.f, wq = 0.f, wk = 0.f;
    for (int p = lane; p < 36; p += 32) {
        int i = c_pi[p], i2 = c_pj[p];
        float m = (i == i2) ? 1.f : 2.f;
        float gq = 0.f, wqp = 0.f, gk = 0.f, wkp = 0.f;
        for (int d = 0; d < 64; d++) {
            float pq = qT[h][d * 8 + i] * qT[h][d * 8 + i2];
            gq += pq; wqp = fmaf(pq, __ldg(&g_Sq[p * 64 + d]), wqp);
            float pk = kT[h][d * 8 + i] * kT[h][d * 8 + i2];
            gk += pk; wkp = fmaf(pk, __ldg(&g_Sk[p * 64 + d]), wkp);
        }
        dsq = fmaf(m * gq, gk, dsq); wq = fmaf(m, wqp, wq); wk = fmaf(m, wkp, wk);
    }
#pragma unroll
    for (int off = 16; off; off >>= 1) {
        dsq += __shfl_xor_sync(~0u, dsq, off);
        wq  += __shfl_xor_sync(~0u, wq,  off);
        wk  += __shfl_xor_sync(~0u, wk,  off);
    }
    __syncwarp();
    if (lane == 0) {
        float ds = 0.f, qs = 0.f, ks = 0.f;
#pragma unroll
        for (int i = 0; i < 8; i++) {
            ds = fmaf(rsq[h][i], rsk[h][i], ds);
            qs += tqs[h][i]; ks += tks[h][i];
        }
        atomicAdd(&g_st[stoff + h * 3 + 0], (double)qs);
        atomicAdd(&g_st[stoff + h * 3 + 1], (double)ks);
        atomicAdd(&g_st[stoff + h * 3 + 2], (double)ds);
        atomicAdd(&g_st[stoff + 24 + h * 3 + 0], (double)wq);
        atomicAdd(&g_st[stoff + 24 + h * 3 + 1], (double)wk);
        atomicAdd(&g_st[stoff + 24 + h * 3 + 2], (double)dsq);
    }
}

// ---------------------------------------------------------------------------
// att_pass2: logits (BN applied) -> softmax -> sv & sve, register-tiled.
// Phase A: 4x4 (d,j) tiles, attn stored transposed satT[j][d].
// Phase B: 2i x 4d tiles, j split across lane halves, sliding rel window.
// ---------------------------------------------------------------------------
__global__ void __launch_bounds__(256) att_pass2(const float* __restrict__ rel,
                                                 int sba, int sto) {
    const int bw = blockIdx.x, h = blockIdx.y, tid = threadIdx.x;
    __shared__ float sq[8][68], sk[8][68], svv[16][68];
    __shared__ float srel[32][129];
    __shared__ float satT[64][68];

#pragma unroll
    for (int r = 0; r < 8; r++) {
        int t = tid + r * 256;
        int o = t >> 6, d = t & 63;
        float v = g_qkv[(o * 8 + h) * NT + bw * 64 + d];
        if (o < 8) sq[o][d] = v;
        else if (o < 16) sk[o - 8][d] = v;
        else svv[o - 16][d] = v;
    }
    for (int t = tid; t < 32 * 127; t += 256) srel[t / 127][t % 127] = rel[t];
    const float s0 = g_sb[sba + h * 3], s1v = g_sb[sba + h * 3 + 1], s2v = g_sb[sba + h * 3 + 2];
    const float bsum = g_sb[sba + 24 + h * 3] + g_sb[sba + 24 + h * 3 + 1]
                     + g_sb[sba + 24 + h * 3 + 2];
    __syncthreads();

    {   // ---- Phase A: logits + softmax ----
        const int ty = tid >> 4, tx = tid & 15;
        const int d0 = ty * 4, j0 = tx * 4;
        const int base = d0 - j0 + 63;
        float aQ[4][4], aK[4][4], aD[4][4];
#pragma unroll
        for (int a = 0; a < 4; a++)
#pragma unroll
            for (int b = 0; b < 4; b++) { aQ[a][b] = 0.f; aK[a][b] = 0.f; aD[a][b] = 0.f; }

#pragma unroll
        for (int i = 0; i < 8; i++) {
            float4 q4 = *(const float4*)&sq[i][d0];
            float4 kj4 = *(const float4*)&sk[i][j0];
            float4 kd4 = *(const float4*)&sk[i][d0];
            float qa[4] = {q4.x, q4.y, q4.z, q4.w};
            float ka[4] = {kj4.x, kj4.y, kj4.z, kj4.w};
            float kda[4] = {kd4.x, kd4.y, kd4.z, kd4.w};
            float rq[7], rk[7];
#pragma unroll
            for (int t = 0; t < 7; t++) {
                rq[t] = srel[i][base - 3 + t];
                rk[t] = srel[8 + i][base - 3 + t];
            }
#pragma unroll
            for (int dd = 0; dd < 4; dd++)
#pragma unroll
                for (int jj = 0; jj < 4; jj++) {
                    aD[dd][jj] = fmaf(qa[dd], ka[jj], aD[dd][jj]);
                    aQ[dd][jj] = fmaf(qa[dd], rq[3 + dd - jj], aQ[dd][jj]);
                    aK[dd][jj] = fmaf(kda[dd], rk[3 + dd - jj], aK[dd][jj]);
                }
        }
        float l[4][4], rmax[4], rsum[4];
#pragma unroll
        for (int dd = 0; dd < 4; dd++) {
            rmax[dd] = -3.4e38f;
#pragma unroll
            for (int jj = 0; jj < 4; jj++) {
                float v = aQ[dd][jj] * s0 + aK[dd][jj] * s1v + aD[dd][jj] * s2v + bsum;
                l[dd][jj] = v;
                rmax[dd] = fmaxf(rmax[dd], v);
            }
        }
#pragma unroll
        for (int off = 1; off < 16; off <<= 1)
#pragma unroll
            for (int dd = 0; dd < 4; dd++)
                rmax[dd] = fmaxf(rmax[dd], __shfl_xor_sync(~0u, rmax[dd], off));
#pragma unroll
        for (int dd = 0; dd < 4; dd++) {
            rsum[dd] = 0.f;
#pragma unroll
            for (int jj = 0; jj < 4; jj++) {
                float e = __expf(l[dd][jj] - rmax[dd]);
                l[dd][jj] = e;
                rsum[dd] += e;
            }
        }
#pragma unroll
        for (int off = 1; off < 16; off <<= 1)
#pragma unroll
            for (int dd = 0; dd < 4; dd++)
                rsum[dd] += __shfl_xor_sync(~0u, rsum[dd], off);
        float rinv[4];
#pragma unroll
        for (int dd = 0; dd < 4; dd++) rinv[dd] = 1.f / rsum[dd];
#pragma unroll
        for (int jj = 0; jj < 4; jj++) {
            float4 p4 = make_float4(l[0][jj] * rinv[0], l[1][jj] * rinv[1],
                                    l[2][jj] * rinv[2], l[3][jj] * rinv[3]);
            *(float4*)&satT[j0 + jj][d0] = p4;
        }
    }
    __syncthreads();

    {   // ---- Phase B: sv & sve ----
        const int ig = tid >> 5;         // 0..7 -> i0 = 2*ig
        const int lane = tid & 31;
        const int dg = lane & 15, d0 = dg * 4;
        const int jh = lane >> 4, jbeg = jh * 32;
        const int i0 = ig * 2;
        float aV0[4] = {}, aV1[4] = {}, aE0[4] = {}, aE1[4] = {};
        float w0[4], w1[4];
#pragma unroll
        for (int t = 0; t < 4; t++) {
            w0[t] = srel[16 + i0][d0 + 63 - jbeg + t];
            w1[t] = srel[17 + i0][d0 + 63 - jbeg + t];
        }
        for (int jj = 0; jj < 32; jj++) {
            int j = jbeg + jj;
            float4 a4 = *(const float4*)&satT[j][d0];
            float aa[4] = {a4.x, a4.y, a4.z, a4.w};
            float v0 = svv[i0][j], v1 = svv[i0 + 1][j];
#pragma unroll
            for (int t = 0; t < 4; t++) {
                aV0[t] = fmaf(aa[t], v0, aV0[t]);
                aV1[t] = fmaf(aa[t], v1, aV1[t]);
                aE0[t] = fmaf(aa[t], w0[t], aE0[t]);
                aE1[t] = fmaf(aa[t], w1[t], aE1[t]);
            }
            if (jj < 31) {
                float n0 = srel[16 + i0][d0 + 62 - j];
                float n1 = srel[17 + i0][d0 + 62 - j];
                w0[3] = w0[2]; w0[2] = w0[1]; w0[1] = w0[0]; w0[0] = n0;
                w1[3] = w1[2]; w1[2] = w1[1]; w1[1] = w1[0]; w1[0] = n1;
            }
        }
#pragma unroll
        for (int t = 0; t < 4; t++) {
            aV0[t] += __shfl_xor_sync(~0u, aV0[t], 16);
            aV1[t] += __shfl_xor_sync(~0u, aV1[t], 16);
            aE0[t] += __shfl_xor_sync(~0u, aE0[t], 16);
            aE1[t] += __shfl_xor_sync(~0u, aE1[t], 16);
        }
        float sv0 = 0, sv1 = 0, se0 = 0, se1 = 0, qv0 = 0, qv1 = 0, qe0 = 0, qe1 = 0;
#pragma unroll
        for (int t = 0; t < 4; t++) {
            sv0 += aV0[t]; qv0 = fmaf(aV0[t], aV0[t], qv0);
            sv1 += aV1[t]; qv1 = fmaf(aV1[t], aV1[t], qv1);
            se0 += aE0[t]; qe0 = fmaf(aE0[t], aE0[t], qe0);
            se1 += aE1[t]; qe1 = fmaf(aE1[t], aE1[t], qe1);
        }
#pragma unroll
        for (int off = 1; off < 16; off <<= 1) {
            sv0 += __shfl_xor_sync(~0u, sv0, off); sv1 += __shfl_xor_sync(~0u, sv1, off);
            se0 += __shfl_xor_sync(~0u, se0, off); se1 += __shfl_xor_sync(~0u, se1, off);
            qv0 += __shfl_xor_sync(~0u, qv0, off); qv1 += __shfl_xor_sync(~0u, qv1, off);
            qe0 += __shfl_xor_sync(~0u, qe0, off); qe1 += __shfl_xor_sync(~0u, qe1, off);
        }
        if (jh == 0) {
            int ch0 = h * 16 + i0, ch1 = ch0 + 1;
            *(float4*)&g_outatt[ch0 * NT + bw * 64 + d0] =
                make_float4(aE0[0], aE0[1], aE0[2], aE0[3]);
            *(float4*)&g_outatt[ch1 * NT + bw * 64 + d0] =
                make_float4(aE1[0], aE1[1], aE1[2], aE1[3]);
            *(float4*)&g_outatt[(128 + ch0) * NT + bw * 64 + d0] =
                make_float4(aV0[0], aV0[1], aV0[2], aV0[3]);
            *(float4*)&g_outatt[(128 + ch1) * NT + bw * 64 + d0] =
                make_float4(aV1[0], aV1[1], aV1[2], aV1[3]);
        }
        if (lane == 0) {
            int ch0 = h * 16 + i0, ch1 = ch0 + 1;
            atomicAdd(&g_st[sto + ch0], (double)se0);
            atomicAdd(&g_st[sto + ch1], (double)se1);
            atomicAdd(&g_st[sto + 256 + ch0], (double)qe0);
            atomicAdd(&g_st[sto + 256 + ch1], (double)qe1);
            atomicAdd(&g_st[sto + 128 + ch0], (double)sv0);
            atomicAdd(&g_st[sto + 128 + ch1], (double)sv1);
            atomicAdd(&g_st[sto + 256 + 128 + ch0], (double)qv0);
            atomicAdd(&g_st[sto + 256 + 128 + ch1], (double)qv1);
        }
    }
}

// combine att1: x3[c][b][h][w] = bn(sve) + bn(sv), with h<->w transpose
__global__ void __launch_bounds__(256) combine1() {
    const int c = blockIdx.x, b = blockIdx.y, tid = threadIdx.x;
    __shared__ float tile[64][65];
    const float sA = g_sb[304 + c],        bA = g_sb[304 + 256 + c];
    const float sB = g_sb[304 + c + 128],  bB = g_sb[304 + 256 + c + 128];
    const float* pA = g_outatt + c * NT + b * 4096;
    const float* pB = g_outatt + (c + 128) * NT + b * 4096;
    for (int t = tid; t < 4096; t += 256)
        tile[t >> 6][t & 63] = pA[t] * sA + bA + pB[t] * sB + bB;
    __syncthreads();
    float* q = g_x3 + c * NT + b * 4096;
    for (int t = tid; t < 4096; t += 256)
        q[t] = tile[t & 63][t >> 6];
}

// combine att2: x4 = relu(bn(sve2) + bn(sv2))
__global__ void __launch_bounds__(256) combine2() {
    int idx = blockIdx.x * 256 + threadIdx.x;
    int c = idx >> 15, m = idx & (NT - 1);
    float v = g_outatt[c * NT + m] * g_sb[864 + c] + g_sb[864 + 256 + c]
            + g_outatt[(c + 128) * NT + m] * g_sb[864 + c + 128] + g_sb[864 + 256 + c + 128];
    g_x3[idx] = fmaxf(v, 0.f);
}

// final: out = relu(bn(conv_out) + x_in)
__global__ void __launch_bounds__(256) final_k(const float* __restrict__ x_in,
                                               float* __restrict__ out) {
    int idx = blockIdx.x * 256 + threadIdx.x;
    int o = idx >> 15, m = idx & (NT - 1);
    int b = m >> 12, hw = m & 4095;
    float v = g_y2[idx] * g_sb[1376 + o] + g_sb[1376 + 256 + o];
    int oidx = (b * 256 + o) * 4096 + hw;
    v += x_in[oidx];
    out[oidx] = fmaxf(v, 0.f);
}

// ---------------------------------------------------------------------------
extern "C" void kernel_launch(void* const* d_in, const int* in_sizes, int n_in,
                              void* d_out, int out_size) {
    (void)in_sizes; (void)n_in; (void)out_size;
    const float* x_in   = (const float*)d_in[0];
    const float* w_in   = (const float*)d_in[1];
    const float* g_in   = (const float*)d_in[2];
    const float* b_in   = (const float*)d_in[3];
    const float* w_out  = (const float*)d_in[4];
    const float* g_out  = (const float*)d_in[5];
    const float* b_out  = (const float*)d_in[6];
    const float* wqkv_h = (const float*)d_in[7];
    const float* rel_h  = (const float*)d_in[8];
    const float* ga_h   = (const float*)d_in[9];
    const float* ba_h   = (const float*)d_in[10];
    const float* go_h   = (const float*)d_in[11];
    const float* bo_h   = (const float*)d_in[12];
    const float* wqkv_w = (const float*)d_in[13];
    const float* rel_w  = (const float*)d_in[14];
    const float* ga_w   = (const float*)d_in[15];
    const float* ba_w   = (const float*)d_in[16];
    const float* go_w   = (const float*)d_in[17];
    const float* bo_w   = (const float*)d_in[18];

    zero_stats<<<8, 256>>>();

    // conv-in (+stats) -> y1
    gemm_k<0><<<dim3(256, 1), 256>>>(w_in, x_in, 256);
    make_scale<<<2, 64>>>(0, g_in, b_in, 0, 128, 1.f / 32768.f);

    // --- axial attention along H ---
    prep_S<<<1, 256>>>(rel_h);
    gemm_k<1><<<dim3(256, 2), 256>>>(wqkv_h, nullptr, 128);
    att_stats<<<512, 256>>>(256);
    make_scale<<<1, 64>>>(256, ga_h, ba_h, 256, 24, 1.f / 2097152.f);
    att_pass2<<<dim3(512, 8), 256>>>(rel_h, 256, 304);
    make_scale<<<4, 64>>>(304, go_h, bo_h, 304, 256, 1.f / 32768.f);
    combine1<<<dim3(128, 8), 256>>>();

    // --- axial attention along W ---
    prep_S<<<1, 256>>>(rel_w);
    gemm_k<2><<<dim3(256, 2), 256>>>(wqkv_w, nullptr, 128);
    att_stats<<<512, 256>>>(816);
    make_scale<<<1, 64>>>(816, ga_w, ba_w, 816, 24, 1.f / 2097152.f);
    att_pass2<<<dim3(512, 8), 256>>>(rel_w, 816, 864);
    make_scale<<<4, 64>>>(864, go_w, bo_w, 864, 256, 1.f / 32768.f);
    combine2<<<16384, 256>>>();

    // conv-out (+stats) -> y2
    gemm_k<3><<<dim3(256, 2), 256>>>(w_out, nullptr, 128);
    make_scale<<<4, 64>>>(1376, g_out, b_out, 1376, 256, 1.f / 32768.f);

    final_k<<<32768, 256>>>(x_in, (float*)d_out);
}

// round 4
// speedup vs baseline: 1.1483x; 1.0774x over previous
#include <cuda_runtime.h>
#include <cstdint>

// ---------------------------------------------------------------------------
// Problem constants
//   B=8, C_IN=256, DIM=64, HEADS=8, D_IN=128, DKQ=8, DV=16, QKV=32
//   N = B*DIM*DIM = 32768 "pixels"; sequences: 512 of length 64
// ---------------------------------------------------------------------------
#define NT 32768
#define EPSV 1e-5f

__device__ float  g_y1[128 * NT];      // conv-in raw output, layout [c][b][w][h]
__device__ float  g_qkv[256 * NT];     // qkv, layout [o][bw][pos]
__device__ float  g_outatt[256 * NT];  // attention out (sve ch 0..127, sv 128..255)
__device__ float  g_x3[128 * NT];      // att combined (also reused as x4)
__device__ float  g_y2[256 * NT];      // conv-out raw output [o][n1]
// stats offsets: convin @0(256) att1 @256(48) out1 @304(512) att2 @816(48)
//                out2 @864(512) convout @1376(512)
__device__ double g_st[1888];
__device__ float  g_sb[1888];

// Precomputed rel-embedding tables (per direction, overwritten between dirs)
__device__ float g_Tq[8 * 64], g_Tk[8 * 64];
__device__ float g_Sq[36 * 64], g_Sk[36 * 64];

__device__ const int c_pi[36] = {0,0,0,0,0,0,0,0, 1,1,1,1,1,1,1, 2,2,2,2,2,2,
                                 3,3,3,3,3, 4,4,4,4, 5,5,5, 6,6, 7};
__device__ const int c_pj[36] = {0,1,2,3,4,5,6,7, 1,2,3,4,5,6,7, 2,3,4,5,6,7,
                                 3,4,5,6,7, 4,5,6,7, 5,6,7, 6,7, 7};

__global__ void zero_stats() {
    int i = blockIdx.x * 256 + threadIdx.x;
    if (i < 1888) g_st[i] = 0.0;
}

__global__ void make_scale(int stoff, const float* __restrict__ gamma,
                           const float* __restrict__ beta, int sboff, int C, float invN) {
    int t = blockIdx.x * 64 + threadIdx.x;
    if (t >= C) return;
    double mean = g_st[stoff + t] * (double)invN;
    double var  = g_st[stoff + C + t] * (double)invN - mean * mean;
    float s = gamma[t] * rsqrtf((float)var + EPSV);
    g_sb[sboff + t]     = s;
    g_sb[sboff + C + t] = beta[t] - (float)mean * s;
}

// ---------------------------------------------------------------------------
// 3xTF32 helpers
// ---------------------------------------------------------------------------
__device__ __forceinline__ void split_tf32(float x, float& hi, float& lo) {
    uint32_t h;
    asm("cvt.rna.tf32.f32 %0, %1;" : "=r"(h) : "f"(x));
    float hf = __uint_as_float(h);
    uint32_t l;
    asm("cvt.rna.tf32.f32 %0, %1;" : "=r"(l) : "f"(x - hf));
    hi = hf;
    lo = __uint_as_float(l);
}

#define MMA_TF32(c, a0, a1, a2, a3, b0, b1)                                    \
    asm volatile(                                                              \
        "mma.sync.aligned.m16n8k8.row.col.f32.tf32.tf32.f32 "                  \
        "{%0,%1,%2,%3}, {%4,%5,%6,%7}, {%8,%9}, {%0,%1,%2,%3};"                \
        : "+f"(c[0]), "+f"(c[1]), "+f"(c[2]), "+f"(c[3])                       \
        : "r"(a0), "r"(a1), "r"(a2), "r"(a3), "r"(b0), "r"(b1))

// ---------------------------------------------------------------------------
// GEMM via 3xTF32 mma.sync: C[MxNT] = A[MxK] * B[KxNT]
// MODE 0 conv-in (gather x_in, scatter to y1 + stats), 1 qkv (BN+relu
// prologue), 2 qkv plain, 3 conv-out (+stats)
// Block tile 128x128, k-chunk 16; 8 warps, warp tile 64(m) x 32(n).
// ---------------------------------------------------------------------------
template <int MODE>
__global__ void __launch_bounds__(256) gemm_k(const float* __restrict__ A,
                                              const float* __restrict__ Bext, int K) {
    __shared__ float Ash[16][136], Asl[16][136];
    __shared__ float Bsh[16][136], Bsl[16][136];
    __shared__ float ssum[128], ssq[128];
    const int n0 = blockIdx.x * 128;
    const int m0 = blockIdx.y * 128;
    const int tid = threadIdx.x;
    const int warp = tid >> 5, lane = tid & 31;
    const int lq = lane & 3, lr = lane >> 2;
    const int mb = (warp & 1) * 64;
    const int nb = (warp >> 1) * 32;

    const float* Bp = (MODE == 0) ? Bext : ((MODE == 1) ? g_y1 : g_x3);
    float* Cp = (MODE == 0) ? g_y1 : ((MODE == 3) ? g_y2 : g_qkv);

    float acc[4][4][4];
#pragma unroll
    for (int mt = 0; mt < 4; mt++)
#pragma unroll
        for (int nt = 0; nt < 4; nt++)
#pragma unroll
            for (int c = 0; c < 4; c++) acc[mt][nt][c] = 0.f;

    for (int k0 = 0; k0 < K; k0 += 16) {
        // stage A tile [m=128][k=16] transposed -> Ash/Asl[k][m]
#pragma unroll
        for (int r = 0; r < 2; r++) {
            int t = tid + r * 256;
            int row = t >> 2, c4 = (t & 3) * 4;
            float4 v = *(const float4*)&A[(m0 + row) * K + k0 + c4];
            float h, l;
            split_tf32(v.x, h, l); Ash[c4 + 0][row] = h; Asl[c4 + 0][row] = l;
            split_tf32(v.y, h, l); Ash[c4 + 1][row] = h; Asl[c4 + 1][row] = l;
            split_tf32(v.z, h, l); Ash[c4 + 2][row] = h; Asl[c4 + 2][row] = l;
            split_tf32(v.w, h, l); Ash[c4 + 3][row] = h; Asl[c4 + 3][row] = l;
        }
        // stage B tile [k=16][n=128]
#pragma unroll
        for (int r = 0; r < 2; r++) {
            int t = tid + r * 256;
            int kr = t >> 5, m4 = (t & 31) * 4;
            float4 v;
            if (MODE == 0) {
                v = *(const float4*)&Bp[(n0 >> 12) * 1048576 + (k0 + kr) * 4096 + (n0 & 4095) + m4];
            } else {
                v = *(const float4*)&Bp[(k0 + kr) * NT + n0 + m4];
                if (MODE == 1) {
                    float s = g_sb[k0 + kr], bi = g_sb[128 + k0 + kr];
                    v.x = fmaxf(fmaf(v.x, s, bi), 0.f);
                    v.y = fmaxf(fmaf(v.y, s, bi), 0.f);
                    v.z = fmaxf(fmaf(v.z, s, bi), 0.f);
                    v.w = fmaxf(fmaf(v.w, s, bi), 0.f);
                }
            }
            float h, l;
            split_tf32(v.x, h, l); Bsh[kr][m4 + 0] = h; Bsl[kr][m4 + 0] = l;
            split_tf32(v.y, h, l); Bsh[kr][m4 + 1] = h; Bsl[kr][m4 + 1] = l;
            split_tf32(v.z, h, l); Bsh[kr][m4 + 2] = h; Bsl[kr][m4 + 2] = l;
            split_tf32(v.w, h, l); Bsh[kr][m4 + 3] = h; Bsl[kr][m4 + 3] = l;
        }
        __syncthreads();

#pragma unroll
        for (int ks = 0; ks < 16; ks += 8) {
            uint32_t bh[4][2], bl[4][2];
#pragma unroll
            for (int nt = 0; nt < 4; nt++) {
                int nn = nb + nt * 8 + lr;
                bh[nt][0] = __float_as_uint(Bsh[ks + lq][nn]);
                bh[nt][1] = __float_as_uint(Bsh[ks + lq + 4][nn]);
                bl[nt][0] = __float_as_uint(Bsl[ks + lq][nn]);
                bl[nt][1] = __float_as_uint(Bsl[ks + lq + 4][nn]);
            }
#pragma unroll
            for (int mt = 0; mt < 4; mt++) {
                int mm = mb + mt * 16 + lr;
                uint32_t ah0 = __float_as_uint(Ash[ks + lq][mm]);
                uint32_t ah1 = __float_as_uint(Ash[ks + lq][mm + 8]);
                uint32_t ah2 = __float_as_uint(Ash[ks + lq + 4][mm]);
                uint32_t ah3 = __float_as_uint(Ash[ks + lq + 4][mm + 8]);
                uint32_t al0 = __float_as_uint(Asl[ks + lq][mm]);
                uint32_t al1 = __float_as_uint(Asl[ks + lq][mm + 8]);
                uint32_t al2 = __float_as_uint(Asl[ks + lq + 4][mm]);
                uint32_t al3 = __float_as_uint(Asl[ks + lq + 4][mm + 8]);
#pragma unroll
                for (int nt = 0; nt < 4; nt++) {
                    MMA_TF32(acc[mt][nt], ah0, ah1, ah2, ah3, bh[nt][0], bh[nt][1]);
                    MMA_TF32(acc[mt][nt], al0, al1, al2, al3, bh[nt][0], bh[nt][1]);
                    MMA_TF32(acc[mt][nt], ah0, ah1, ah2, ah3, bl[nt][0], bl[nt][1]);
                }
            }
        }
        __syncthreads();
    }

    if (MODE == 0 || MODE == 3) {
        for (int t = tid; t < 128; t += 256) { ssum[t] = 0.f; ssq[t] = 0.f; }
        __syncthreads();
    }

    if (MODE == 0) {
        const int bb = n0 >> 12, hw0 = n0 & 4095;
#pragma unroll
        for (int mt = 0; mt < 4; mt++) {
#pragma unroll
            for (int half = 0; half < 2; half++) {
                int o = mb + mt * 16 + lr + half * 8;  // m0 == 0
                float rs = 0.f, rq = 0.f;
#pragma unroll
                for (int nt = 0; nt < 4; nt++) {
#pragma unroll
                    for (int cc = 0; cc < 2; cc++) {
                        int hw = hw0 + nb + nt * 8 + 2 * lq + cc;
                        float v = acc[mt][nt][half * 2 + cc];
                        Cp[o * NT + bb * 4096 + (hw & 63) * 64 + (hw >> 6)] = v;
                        rs += v; rq += v * v;
                    }
                }
                atomicAdd(&ssum[o], rs);
                atomicAdd(&ssq[o], rq);
            }
        }
    } else {
#pragma unroll
        for (int mt = 0; mt < 4; mt++) {
#pragma unroll
            for (int half = 0; half < 2; half++) {
                int o = m0 + mb + mt * 16 + lr + half * 8;
                float rs = 0.f, rq = 0.f;
#pragma unroll
                for (int nt = 0; nt < 4; nt++) {
                    float2 v2 = make_float2(acc[mt][nt][half * 2], acc[mt][nt][half * 2 + 1]);
                    *(float2*)&Cp[o * NT + n0 + nb + nt * 8 + 2 * lq] = v2;
                    if (MODE == 3) { rs += v2.x + v2.y; rq += v2.x * v2.x + v2.y * v2.y; }
                }
                if (MODE == 3) {
                    atomicAdd(&ssum[o - m0], rs);
                    atomicAdd(&ssq[o - m0], rq);
                }
            }
        }
    }

    if (MODE == 0 || MODE == 3) {
        __syncthreads();
        const int base = (MODE == 0) ? 0 : 1376;
        const int Csz  = (MODE == 0) ? 128 : 256;
        if (tid < 128) {
            atomicAdd(&g_st[base + m0 + tid], (double)ssum[tid]);
            atomicAdd(&g_st[base + Csz + m0 + tid], (double)ssq[tid]);
        }
    }
}

// ---------------------------------------------------------------------------
// prep_S: precompute sliding-window tables of the rel embedding (grid-stride).
// ---------------------------------------------------------------------------
__global__ void __launch_bounds__(256) prep_S(const float* __restrict__ rel) {
    __shared__ float r[16][127];
    for (int t = threadIdx.x; t < 16 * 127; t += 256) r[t / 127][t % 127] = rel[t];
    __syncthreads();
    const int g0 = blockIdx.x * 256 + threadIdx.x;
    const int gs = gridDim.x * 256;
    for (int t = g0; t < 1024; t += gs) {
        int which = t >> 9, i = (t >> 6) & 7, d = t & 63;
        const float* rr = r[which * 8 + i];
        float s = 0.f;
        for (int u = 0; u < 64; u++) s += rr[d + u];
        (which ? g_Tk : g_Tq)[i * 64 + d] = s;
    }
    for (int t = g0; t < 4608; t += gs) {
        int which = t / 2304, rem = t % 2304, p = rem >> 6, d = rem & 63;
        const float* a = r[which * 8 + c_pi[p]];
        const float* b = r[which * 8 + c_pj[p]];
        float s = 0.f;
        for (int u = 0; u < 64; u++) s = fmaf(a[d + u], b[d + u], s);
        (which ? g_Sk : g_Sq)[p * 64 + d] = s;
    }
}

// ---------------------------------------------------------------------------
// att_stats: BN statistics of qr/kr/dots without materializing logits.
// ---------------------------------------------------------------------------
__global__ void __launch_bounds__(256) att_stats(int stoff) {
    const int bw = blockIdx.x, tid = threadIdx.x;
    __shared__ float qT[8][512];   // [h][d*8 + i]
    __shared__ float kT[8][512];
    __shared__ float rsq[8][8], rsk[8][8], tqs[8][8], tks[8][8];

    for (int t = tid; t < 8192; t += 256) {
        int which = t >> 12, o = (t >> 6) & 63, d = t & 63;
        float v = g_qkv[(which * 64 + o) * NT + bw * 64 + d];
        int h = o & 7, i = o >> 3;
        if (which == 0) qT[h][d * 8 + i] = v; else kT[h][d * 8 + i] = v;
    }
    __syncthreads();

    const int h = tid >> 5, lane = tid & 31;
    if (lane < 8) {
        float s = 0.f;
        for (int d = 0; d < 64; d++) s += qT[h][d * 8 + lane];
        rsq[h][lane] = s;
    } else if (lane < 16) {
        int i = lane - 8; float s = 0.f;
        for (int d = 0; d < 64; d++) s += kT[h][d * 8 + i];
        rsk[h][i] = s;
    } else if (lane < 24) {
        int i = lane - 16; float s = 0.f;
        for (int d = 0; d < 64; d++) s = fmaf(qT[h][d * 8 + i], __ldg(&g_Tq[i * 64 + d]), s);
        tqs[h][i] = s;
    } else {
        int i = lane - 24; float s = 0.f;
        for (int d = 0; d < 64; d++) s = fmaf(kT[h][d * 8 + i], __ldg(&g_Tk[i * 64 + d]), s);
        tks[h][i] = s;
    }

    float dsq = 0.f, wq = 0.f, wk = 0.f;
    for (int p = lane; p < 36; p += 32) {
        int i = c_pi[p], i2 = c_pj[p];
        float m = (i == i2) ? 1.f : 2.f;
        float gq = 0.f, wqp = 0.f, gk = 0.f, wkp = 0.f;
        for (int d = 0; d < 64; d++) {
            float pq = qT[h][d * 8 + i] * qT[h][d * 8 + i2];
            gq += pq; wqp = fmaf(pq, __ldg(&g_Sq[p * 64 + d]), wqp);
            float pk = kT[h][d * 8 + i] * kT[h][d * 8 + i2];
            gk += pk; wkp = fmaf(pk, __ldg(&g_Sk[p * 64 + d]), wkp);
        }
        dsq = fmaf(m * gq, gk, dsq); wq = fmaf(m, wqp, wq); wk = fmaf(m, wkp, wk);
    }
#pragma unroll
    for (int off = 16; off; off >>= 1) {
        dsq += __shfl_xor_sync(~0u, dsq, off);
        wq  += __shfl_xor_sync(~0u, wq,  off);
        wk  += __shfl_xor_sync(~0u, wk,  off);
    }
    __syncwarp();
    if (lane == 0) {
        float ds = 0.f, qs = 0.f, ks = 0.f;
#pragma unroll
        for (int i = 0; i < 8; i++) {
            ds = fmaf(rsq[h][i], rsk[h][i], ds);
            qs += tqs[h][i]; ks += tks[h][i];
        }
        atomicAdd(&g_st[stoff + h * 3 + 0], (double)qs);
        atomicAdd(&g_st[stoff + h * 3 + 1], (double)ks);
        atomicAdd(&g_st[stoff + h * 3 + 2], (double)ds);
        atomicAdd(&g_st[stoff + 24 + h * 3 + 0], (double)wq);
        atomicAdd(&g_st[stoff + 24 + h * 3 + 1], (double)wk);
        atomicAdd(&g_st[stoff + 24 + h * 3 + 2], (double)dsq);
    }
}

// ---------------------------------------------------------------------------
// att_pass2: logits (BN applied) -> softmax -> sv & sve, register-tiled.
// ---------------------------------------------------------------------------
__global__ void __launch_bounds__(256) att_pass2(const float* __restrict__ rel,
                                                 int sba, int sto) {
    const int bw = blockIdx.x, h = blockIdx.y, tid = threadIdx.x;
    __shared__ float sq[8][68], sk[8][68], svv[16][68];
    __shared__ float srel[32][129];
    __shared__ float satT[64][68];

#pragma unroll
    for (int r = 0; r < 8; r++) {
        int t = tid + r * 256;
        int o = t >> 6, d = t & 63;
        float v = g_qkv[(o * 8 + h) * NT + bw * 64 + d];
        if (o < 8) sq[o][d] = v;
        else if (o < 16) sk[o - 8][d] = v;
        else svv[o - 16][d] = v;
    }
    for (int t = tid; t < 32 * 127; t += 256) srel[t / 127][t % 127] = rel[t];
    const float s0 = g_sb[sba + h * 3], s1v = g_sb[sba + h * 3 + 1], s2v = g_sb[sba + h * 3 + 2];
    const float bsum = g_sb[sba + 24 + h * 3] + g_sb[sba + 24 + h * 3 + 1]
                     + g_sb[sba + 24 + h * 3 + 2];
    __syncthreads();

    {   // ---- Phase A: logits + softmax ----
        const int ty = tid >> 4, tx = tid & 15;
        const int d0 = ty * 4, j0 = tx * 4;
        const int base = d0 - j0 + 63;
        float aQ[4][4], aK[4][4], aD[4][4];
#pragma unroll
        for (int a = 0; a < 4; a++)
#pragma unroll
            for (int b = 0; b < 4; b++) { aQ[a][b] = 0.f; aK[a][b] = 0.f; aD[a][b] = 0.f; }

#pragma unroll
        for (int i = 0; i < 8; i++) {
            float4 q4 = *(const float4*)&sq[i][d0];
            float4 kj4 = *(const float4*)&sk[i][j0];
            float4 kd4 = *(const float4*)&sk[i][d0];
            float qa[4] = {q4.x, q4.y, q4.z, q4.w};
            float ka[4] = {kj4.x, kj4.y, kj4.z, kj4.w};
            float kda[4] = {kd4.x, kd4.y, kd4.z, kd4.w};
            float rq[7], rk[7];
#pragma unroll
            for (int t = 0; t < 7; t++) {
                rq[t] = srel[i][base - 3 + t];
                rk[t] = srel[8 + i][base - 3 + t];
            }
#pragma unroll
            for (int dd = 0; dd < 4; dd++)
#pragma unroll
                for (int jj = 0; jj < 4; jj++) {
                    aD[dd][jj] = fmaf(qa[dd], ka[jj], aD[dd][jj]);
                    aQ[dd][jj] = fmaf(qa[dd], rq[3 + dd - jj], aQ[dd][jj]);
                    aK[dd][jj] = fmaf(kda[dd], rk[3 + dd - jj], aK[dd][jj]);
                }
        }
        float l[4][4], rmax[4], rsum[4];
#pragma unroll
        for (int dd = 0; dd < 4; dd++) {
            rmax[dd] = -3.4e38f;
#pragma unroll
            for (int jj = 0; jj < 4; jj++) {
                float v = aQ[dd][jj] * s0 + aK[dd][jj] * s1v + aD[dd][jj] * s2v + bsum;
                l[dd][jj] = v;
                rmax[dd] = fmaxf(rmax[dd], v);
            }
        }
#pragma unroll
        for (int off = 1; off < 16; off <<= 1)
#pragma unroll
            for (int dd = 0; dd < 4; dd++)
                rmax[dd] = fmaxf(rmax[dd], __shfl_xor_sync(~0u, rmax[dd], off));
#pragma unroll
        for (int dd = 0; dd < 4; dd++) {
            rsum[dd] = 0.f;
#pragma unroll
            for (int jj = 0; jj < 4; jj++) {
                float e = __expf(l[dd][jj] - rmax[dd]);
                l[dd][jj] = e;
                rsum[dd] += e;
            }
        }
#pragma unroll
        for (int off = 1; off < 16; off <<= 1)
#pragma unroll
            for (int dd = 0; dd < 4; dd++)
                rsum[dd] += __shfl_xor_sync(~0u, rsum[dd], off);
        float rinv[4];
#pragma unroll
        for (int dd = 0; dd < 4; dd++) rinv[dd] = 1.f / rsum[dd];
#pragma unroll
        for (int jj = 0; jj < 4; jj++) {
            float4 p4 = make_float4(l[0][jj] * rinv[0], l[1][jj] * rinv[1],
                                    l[2][jj] * rinv[2], l[3][jj] * rinv[3]);
            *(float4*)&satT[j0 + jj][d0] = p4;
        }
    }
    __syncthreads();

    {   // ---- Phase B: sv & sve ----
        const int ig = tid >> 5;
        const int lane = tid & 31;
        const int dg = lane & 15, d0 = dg * 4;
        const int jh = lane >> 4, jbeg = jh * 32;
        const int i0 = ig * 2;
        float aV0[4] = {}, aV1[4] = {}, aE0[4] = {}, aE1[4] = {};
        float w0[4], w1[4];
#pragma unroll
        for (int t = 0; t < 4; t++) {
            w0[t] = srel[16 + i0][d0 + 63 - jbeg + t];
            w1[t] = srel[17 + i0][d0 + 63 - jbeg + t];
        }
        for (int jj = 0; jj < 32; jj++) {
            int j = jbeg + jj;
            float4 a4 = *(const float4*)&satT[j][d0];
            float aa[4] = {a4.x, a4.y, a4.z, a4.w};
            float v0 = svv[i0][j], v1 = svv[i0 + 1][j];
#pragma unroll
            for (int t = 0; t < 4; t++) {
                aV0[t] = fmaf(aa[t], v0, aV0[t]);
                aV1[t] = fmaf(aa[t], v1, aV1[t]);
                aE0[t] = fmaf(aa[t], w0[t], aE0[t]);
                aE1[t] = fmaf(aa[t], w1[t], aE1[t]);
            }
            if (jj < 31) {
                float n0 = srel[16 + i0][d0 + 62 - j];
                float n1 = srel[17 + i0][d0 + 62 - j];
                w0[3] = w0[2]; w0[2] = w0[1]; w0[1] = w0[0]; w0[0] = n0;
                w1[3] = w1[2]; w1[2] = w1[1]; w1[1] = w1[0]; w1[0] = n1;
            }
        }
#pragma unroll
        for (int t = 0; t < 4; t++) {
            aV0[t] += __shfl_xor_sync(~0u, aV0[t], 16);
            aV1[t] += __shfl_xor_sync(~0u, aV1[t], 16);
            aE0[t] += __shfl_xor_sync(~0u, aE0[t], 16);
            aE1[t] += __shfl_xor_sync(~0u, aE1[t], 16);
        }
        float sv0 = 0, sv1 = 0, se0 = 0, se1 = 0, qv0 = 0, qv1 = 0, qe0 = 0, qe1 = 0;
#pragma unroll
        for (int t = 0; t < 4; t++) {
            sv0 += aV0[t]; qv0 = fmaf(aV0[t], aV0[t], qv0);
            sv1 += aV1[t]; qv1 = fmaf(aV1[t], aV1[t], qv1);
            se0 += aE0[t]; qe0 = fmaf(aE0[t], aE0[t], qe0);
            se1 += aE1[t]; qe1 = fmaf(aE1[t], aE1[t], qe1);
        }
#pragma unroll
        for (int off = 1; off < 16; off <<= 1) {
            sv0 += __shfl_xor_sync(~0u, sv0, off); sv1 += __shfl_xor_sync(~0u, sv1, off);
            se0 += __shfl_xor_sync(~0u, se0, off); se1 += __shfl_xor_sync(~0u, se1, off);
            qv0 += __shfl_xor_sync(~0u, qv0, off); qv1 += __shfl_xor_sync(~0u, qv1, off);
            qe0 += __shfl_xor_sync(~0u, qe0, off); qe1 += __shfl_xor_sync(~0u, qe1, off);
        }
        if (jh == 0) {
            int ch0 = h * 16 + i0, ch1 = ch0 + 1;
            *(float4*)&g_outatt[ch0 * NT + bw * 64 + d0] =
                make_float4(aE0[0], aE0[1], aE0[2], aE0[3]);
            *(float4*)&g_outatt[ch1 * NT + bw * 64 + d0] =
                make_float4(aE1[0], aE1[1], aE1[2], aE1[3]);
            *(float4*)&g_outatt[(128 + ch0) * NT + bw * 64 + d0] =
                make_float4(aV0[0], aV0[1], aV0[2], aV0[3]);
            *(float4*)&g_outatt[(128 + ch1) * NT + bw * 64 + d0] =
                make_float4(aV1[0], aV1[1], aV1[2], aV1[3]);
        }
        if (lane == 0) {
            int ch0 = h * 16 + i0, ch1 = ch0 + 1;
            atomicAdd(&g_st[sto + ch0], (double)se0);
            atomicAdd(&g_st[sto + ch1], (double)se1);
            atomicAdd(&g_st[sto + 256 + ch0], (double)qe0);
            atomicAdd(&g_st[sto + 256 + ch1], (double)qe1);
            atomicAdd(&g_st[sto + 128 + ch0], (double)sv0);
            atomicAdd(&g_st[sto + 128 + ch1], (double)sv1);
            atomicAdd(&g_st[sto + 256 + 128 + ch0], (double)qv0);
            atomicAdd(&g_st[sto + 256 + 128 + ch1], (double)qv1);
        }
    }
}

// combine att1: x3[c][b][h][w] = bn(sve) + bn(sv), with h<->w transpose
__global__ void __launch_bounds__(256) combine1() {
    const int c = blockIdx.x, b = blockIdx.y, tid = threadIdx.x;
    __shared__ float tile[64][65];
    const float sA = g_sb[304 + c],        bA = g_sb[304 + 256 + c];
    const float sB = g_sb[304 + c + 128],  bB = g_sb[304 + 256 + c + 128];
    const float* pA = g_outatt + c * NT + b * 4096;
    const float* pB = g_outatt + (c + 128) * NT + b * 4096;
    for (int t = tid; t < 4096; t += 256)
        tile[t >> 6][t & 63] = pA[t] * sA + bA + pB[t] * sB + bB;
    __syncthreads();
    float* q = g_x3 + c * NT + b * 4096;
    for (int t = tid; t < 4096; t += 256)
        q[t] = tile[t & 63][t >> 6];
}

// combine att2: x4 = relu(bn(sve2) + bn(sv2))
__global__ void __launch_bounds__(256) combine2() {
    int idx = blockIdx.x * 256 + threadIdx.x;
    int c = idx >> 15, m = idx & (NT - 1);
    float v = g_outatt[c * NT + m] * g_sb[864 + c] + g_sb[864 + 256 + c]
            + g_outatt[(c + 128) * NT + m] * g_sb[864 + c + 128] + g_sb[864 + 256 + c + 128];
    g_x3[idx] = fmaxf(v, 0.f);
}

// final: out = relu(bn(conv_out) + x_in)
__global__ void __launch_bounds__(256) final_k(const float* __restrict__ x_in,
                                               float* __restrict__ out) {
    int idx = blockIdx.x * 256 + threadIdx.x;
    int o = idx >> 15, m = idx & (NT - 1);
    int b = m >> 12, hw = m & 4095;
    float v = g_y2[idx] * g_sb[1376 + o] + g_sb[1376 + 256 + o];
    int oidx = (b * 256 + o) * 4096 + hw;
    v += x_in[oidx];
    out[oidx] = fmaxf(v, 0.f);
}

// ---------------------------------------------------------------------------
extern "C" void kernel_launch(void* const* d_in, const int* in_sizes, int n_in,
                              void* d_out, int out_size) {
    (void)in_sizes; (void)n_in; (void)out_size;
    const float* x_in   = (const float*)d_in[0];
    const float* w_in   = (const float*)d_in[1];
    const float* g_in   = (const float*)d_in[2];
    const float* b_in   = (const float*)d_in[3];
    const float* w_out  = (const float*)d_in[4];
    const float* g_out  = (const float*)d_in[5];
    const float* b_out  = (const float*)d_in[6];
    const float* wqkv_h = (const float*)d_in[7];
    const float* rel_h  = (const float*)d_in[8];
    const float* ga_h   = (const float*)d_in[9];
    const float* ba_h   = (const float*)d_in[10];
    const float* go_h   = (const float*)d_in[11];
    const float* bo_h   = (const float*)d_in[12];
    const float* wqkv_w = (const float*)d_in[13];
    const float* rel_w  = (const float*)d_in[14];
    const float* ga_w   = (const float*)d_in[15];
    const float* ba_w   = (const float*)d_in[16];
    const float* go_w   = (const float*)d_in[17];
    const float* bo_w   = (const float*)d_in[18];

    zero_stats<<<8, 256>>>();

    // conv-in (+stats) -> y1
    gemm_k<0><<<dim3(256, 1), 256>>>(w_in, x_in, 256);
    make_scale<<<2, 64>>>(0, g_in, b_in, 0, 128, 1.f / 32768.f);

    // --- axial attention along H ---
    prep_S<<<23, 256>>>(rel_h);
    gemm_k<1><<<dim3(256, 2), 256>>>(wqkv_h, nullptr, 128);
    att_stats<<<512, 256>>>(256);
    make_scale<<<1, 64>>>(256, ga_h, ba_h, 256, 24, 1.f / 2097152.f);
    att_pass2<<<dim3(512, 8), 256>>>(rel_h, 256, 304);
    make_scale<<<4, 64>>>(304, go_h, bo_h, 304, 256, 1.f / 32768.f);
    combine1<<<dim3(128, 8), 256>>>();

    // --- axial attention along W ---
    prep_S<<<23, 256>>>(rel_w);
    gemm_k<2><<<dim3(256, 2), 256>>>(wqkv_w, nullptr, 128);
    att_stats<<<512, 256>>>(816);
    make_scale<<<1, 64>>>(816, ga_w, ba_w, 816, 24, 1.f / 2097152.f);
    att_pass2<<<dim3(512, 8), 256>>>(rel_w, 816, 864);
    make_scale<<<4, 64>>>(864, go_w, bo_w, 864, 256, 1.f / 32768.f);
    combine2<<<16384, 256>>>();

    // conv-out (+stats) -> y2
    gemm_k<3><<<dim3(256, 2), 256>>>(w_out, nullptr, 128);
    make_scale<<<4, 64>>>(1376, g_out, b_out, 1376, 256, 1.f / 32768.f);

    final_k<<<32768, 256>>>(x_in, (float*)d_out);
}

// round 5
// speedup vs baseline: 1.1554x; 1.0062x over previous
#include <cuda_runtime.h>
#include <cstdint>

// ---------------------------------------------------------------------------
// Problem constants
//   B=8, C_IN=256, DIM=64, HEADS=8, D_IN=128, DKQ=8, DV=16, QKV=32
//   N = B*DIM*DIM = 32768 "pixels"; sequences: 512 of length 64
// ---------------------------------------------------------------------------
#define NT 32768
#define EPSV 1e-5f

__device__ float  g_y1[128 * NT];      // conv-in raw output, layout [c][b][w][h]
__device__ float  g_qkv[256 * NT];     // qkv, layout [o][bw][pos]
__device__ float  g_outatt[256 * NT];  // attention out (sve ch 0..127, sv 128..255)
__device__ float  g_x3[128 * NT];      // att1 combined (input to qkv2 GEMM)
__device__ float  g_y2[256 * NT];      // conv-out raw output [o][n1]
// stats offsets: convin @0(256) att1 @256(48) out1 @304(512) att2 @816(48)
//                out2 @864(512) convout @1376(512)
__device__ double g_st[1888];
__device__ float  g_sb[1888];

// Precomputed rel-embedding tables, double-buffered per direction
__device__ float g_Tq[2][8 * 64], g_Tk[2][8 * 64];
__device__ float g_Sq[2][36 * 64], g_Sk[2][36 * 64];

__device__ const int c_pi[36] = {0,0,0,0,0,0,0,0, 1,1,1,1,1,1,1, 2,2,2,2,2,2,
                                 3,3,3,3,3, 4,4,4,4, 5,5,5, 6,6, 7};
__device__ const int c_pj[36] = {0,1,2,3,4,5,6,7, 1,2,3,4,5,6,7, 2,3,4,5,6,7,
                                 3,4,5,6,7, 4,5,6,7, 5,6,7, 6,7, 7};

__global__ void zero_stats() {
    int i = blockIdx.x * 256 + threadIdx.x;
    if (i < 1888) g_st[i] = 0.0;
}

__global__ void make_scale(int stoff, const float* __restrict__ gamma,
                           const float* __restrict__ beta, int sboff, int C, float invN) {
    int t = blockIdx.x * 64 + threadIdx.x;
    if (t >= C) return;
    double mean = g_st[stoff + t] * (double)invN;
    double var  = g_st[stoff + C + t] * (double)invN - mean * mean;
    float s = gamma[t] * rsqrtf((float)var + EPSV);
    g_sb[sboff + t]     = s;
    g_sb[sboff + C + t] = beta[t] - (float)mean * s;
}

// ---------------------------------------------------------------------------
// 3xTF32 helpers
// ---------------------------------------------------------------------------
__device__ __forceinline__ void split_tf32(float x, float& hi, float& lo) {
    uint32_t h;
    asm("cvt.rna.tf32.f32 %0, %1;" : "=r"(h) : "f"(x));
    float hf = __uint_as_float(h);
    uint32_t l;
    asm("cvt.rna.tf32.f32 %0, %1;" : "=r"(l) : "f"(x - hf));
    hi = hf;
    lo = __uint_as_float(l);
}

#define MMA_TF32(c, a0, a1, a2, a3, b0, b1)                                    \
    asm volatile(                                                              \
        "mma.sync.aligned.m16n8k8.row.col.f32.tf32.tf32.f32 "                  \
        "{%0,%1,%2,%3}, {%4,%5,%6,%7}, {%8,%9}, {%0,%1,%2,%3};"                \
        : "+f"(c[0]), "+f"(c[1]), "+f"(c[2]), "+f"(c[3])                       \
        : "r"(a0), "r"(a1), "r"(a2), "r"(a3), "r"(b0), "r"(b1))

// ---------------------------------------------------------------------------
// GEMM via 3xTF32 mma.sync: C[MxNT] = A[MxK] * B[KxNT]
// MODE 0 conv-in (gather x_in, scatter to y1 + stats), 1 qkv (BN+relu
// prologue), 2 qkv plain (reads x3), 3 conv-out (combine2 fused prologue
// reading g_outatt, + stats epilogue)
// ---------------------------------------------------------------------------
template <int MODE>
__global__ void __launch_bounds__(256) gemm_k(const float* __restrict__ A,
                                              const float* __restrict__ Bext, int K) {
    __shared__ float Ash[16][136], Asl[16][136];
    __shared__ float Bsh[16][136], Bsl[16][136];
    __shared__ float ssum[128], ssq[128];
    const int n0 = blockIdx.x * 128;
    const int m0 = blockIdx.y * 128;
    const int tid = threadIdx.x;
    const int warp = tid >> 5, lane = tid & 31;
    const int lq = lane & 3, lr = lane >> 2;
    const int mb = (warp & 1) * 64;
    const int nb = (warp >> 1) * 32;

    const float* Bp = (MODE == 0) ? Bext : ((MODE == 1) ? g_y1 : g_x3);
    float* Cp = (MODE == 0) ? g_y1 : ((MODE == 3) ? g_y2 : g_qkv);

    float acc[4][4][4];
#pragma unroll
    for (int mt = 0; mt < 4; mt++)
#pragma unroll
        for (int nt = 0; nt < 4; nt++)
#pragma unroll
            for (int c = 0; c < 4; c++) acc[mt][nt][c] = 0.f;

    for (int k0 = 0; k0 < K; k0 += 16) {
        // stage A tile [m=128][k=16] transposed -> Ash/Asl[k][m]
#pragma unroll
        for (int r = 0; r < 2; r++) {
            int t = tid + r * 256;
            int row = t >> 2, c4 = (t & 3) * 4;
            float4 v = *(const float4*)&A[(m0 + row) * K + k0 + c4];
            float h, l;
            split_tf32(v.x, h, l); Ash[c4 + 0][row] = h; Asl[c4 + 0][row] = l;
            split_tf32(v.y, h, l); Ash[c4 + 1][row] = h; Asl[c4 + 1][row] = l;
            split_tf32(v.z, h, l); Ash[c4 + 2][row] = h; Asl[c4 + 2][row] = l;
            split_tf32(v.w, h, l); Ash[c4 + 3][row] = h; Asl[c4 + 3][row] = l;
        }
        // stage B tile [k=16][n=128]
#pragma unroll
        for (int r = 0; r < 2; r++) {
            int t = tid + r * 256;
            int kr = t >> 5, m4 = (t & 31) * 4;
            float4 v;
            if (MODE == 0) {
                v = *(const float4*)&Bp[(n0 >> 12) * 1048576 + (k0 + kr) * 4096 + (n0 & 4095) + m4];
            } else if (MODE == 3) {
                // fused combine2: x4 = relu(bn(sve) + bn(sv))
                int c = k0 + kr;
                float4 a = *(const float4*)&g_outatt[c * NT + n0 + m4];
                float4 b = *(const float4*)&g_outatt[(128 + c) * NT + n0 + m4];
                float sA = g_sb[864 + c],       bA = g_sb[864 + 256 + c];
                float sB = g_sb[864 + 128 + c], bB = g_sb[864 + 256 + 128 + c];
                v.x = fmaxf(a.x * sA + bA + b.x * sB + bB, 0.f);
                v.y = fmaxf(a.y * sA + bA + b.y * sB + bB, 0.f);
                v.z = fmaxf(a.z * sA + bA + b.z * sB + bB, 0.f);
                v.w = fmaxf(a.w * sA + bA + b.w * sB + bB, 0.f);
            } else {
                v = *(const float4*)&Bp[(k0 + kr) * NT + n0 + m4];
                if (MODE == 1) {
                    float s = g_sb[k0 + kr], bi = g_sb[128 + k0 + kr];
                    v.x = fmaxf(fmaf(v.x, s, bi), 0.f);
                    v.y = fmaxf(fmaf(v.y, s, bi), 0.f);
                    v.z = fmaxf(fmaf(v.z, s, bi), 0.f);
                    v.w = fmaxf(fmaf(v.w, s, bi), 0.f);
                }
            }
            float h, l;
            split_tf32(v.x, h, l); Bsh[kr][m4 + 0] = h; Bsl[kr][m4 + 0] = l;
            split_tf32(v.y, h, l); Bsh[kr][m4 + 1] = h; Bsl[kr][m4 + 1] = l;
            split_tf32(v.z, h, l); Bsh[kr][m4 + 2] = h; Bsl[kr][m4 + 2] = l;
            split_tf32(v.w, h, l); Bsh[kr][m4 + 3] = h; Bsl[kr][m4 + 3] = l;
        }
        __syncthreads();

#pragma unroll
        for (int ks = 0; ks < 16; ks += 8) {
            uint32_t bh[4][2], bl[4][2];
#pragma unroll
            for (int nt = 0; nt < 4; nt++) {
                int nn = nb + nt * 8 + lr;
                bh[nt][0] = __float_as_uint(Bsh[ks + lq][nn]);
                bh[nt][1] = __float_as_uint(Bsh[ks + lq + 4][nn]);
                bl[nt][0] = __float_as_uint(Bsl[ks + lq][nn]);
                bl[nt][1] = __float_as_uint(Bsl[ks + lq + 4][nn]);
            }
#pragma unroll
            for (int mt = 0; mt < 4; mt++) {
                int mm = mb + mt * 16 + lr;
                uint32_t ah0 = __float_as_uint(Ash[ks + lq][mm]);
                uint32_t ah1 = __float_as_uint(Ash[ks + lq][mm + 8]);
                uint32_t ah2 = __float_as_uint(Ash[ks + lq + 4][mm]);
                uint32_t ah3 = __float_as_uint(Ash[ks + lq + 4][mm + 8]);
                uint32_t al0 = __float_as_uint(Asl[ks + lq][mm]);
                uint32_t al1 = __float_as_uint(Asl[ks + lq][mm + 8]);
                uint32_t al2 = __float_as_uint(Asl[ks + lq + 4][mm]);
                uint32_t al3 = __float_as_uint(Asl[ks + lq + 4][mm + 8]);
#pragma unroll
                for (int nt = 0; nt < 4; nt++) {
                    MMA_TF32(acc[mt][nt], ah0, ah1, ah2, ah3, bh[nt][0], bh[nt][1]);
                    MMA_TF32(acc[mt][nt], al0, al1, al2, al3, bh[nt][0], bh[nt][1]);
                    MMA_TF32(acc[mt][nt], ah0, ah1, ah2, ah3, bl[nt][0], bl[nt][1]);
                }
            }
        }
        __syncthreads();
    }

    if (MODE == 0 || MODE == 3) {
        for (int t = tid; t < 128; t += 256) { ssum[t] = 0.f; ssq[t] = 0.f; }
        __syncthreads();
    }

    if (MODE == 0) {
        const int bb = n0 >> 12, hw0 = n0 & 4095;
#pragma unroll
        for (int mt = 0; mt < 4; mt++) {
#pragma unroll
            for (int half = 0; half < 2; half++) {
                int o = mb + mt * 16 + lr + half * 8;  // m0 == 0
                float rs = 0.f, rq = 0.f;
#pragma unroll
                for (int nt = 0; nt < 4; nt++) {
#pragma unroll
                    for (int cc = 0; cc < 2; cc++) {
                        int hw = hw0 + nb + nt * 8 + 2 * lq + cc;
                        float v = acc[mt][nt][half * 2 + cc];
                        Cp[o * NT + bb * 4096 + (hw & 63) * 64 + (hw >> 6)] = v;
                        rs += v; rq += v * v;
                    }
                }
                atomicAdd(&ssum[o], rs);
                atomicAdd(&ssq[o], rq);
            }
        }
    } else {
#pragma unroll
        for (int mt = 0; mt < 4; mt++) {
#pragma unroll
            for (int half = 0; half < 2; half++) {
                int o = m0 + mb + mt * 16 + lr + half * 8;
                float rs = 0.f, rq = 0.f;
#pragma unroll
                for (int nt = 0; nt < 4; nt++) {
                    float2 v2 = make_float2(acc[mt][nt][half * 2], acc[mt][nt][half * 2 + 1]);
                    *(float2*)&Cp[o * NT + n0 + nb + nt * 8 + 2 * lq] = v2;
                    if (MODE == 3) { rs += v2.x + v2.y; rq += v2.x * v2.x + v2.y * v2.y; }
                }
                if (MODE == 3) {
                    atomicAdd(&ssum[o - m0], rs);
                    atomicAdd(&ssq[o - m0], rq);
                }
            }
        }
    }

    if (MODE == 0 || MODE == 3) {
        __syncthreads();
        const int base = (MODE == 0) ? 0 : 1376;
        const int Csz  = (MODE == 0) ? 128 : 256;
        if (tid < 128) {
            atomicAdd(&g_st[base + m0 + tid], (double)ssum[tid]);
            atomicAdd(&g_st[base + Csz + m0 + tid], (double)ssq[tid]);
        }
    }
}

// ---------------------------------------------------------------------------
// prep_S: precompute sliding-window tables of the rel embedding (grid-stride).
// ---------------------------------------------------------------------------
__global__ void __launch_bounds__(256) prep_S(const float* __restrict__ rel, int dir) {
    __shared__ float r[16][127];
    for (int t = threadIdx.x; t < 16 * 127; t += 256) r[t / 127][t % 127] = rel[t];
    __syncthreads();
    const int g0 = blockIdx.x * 256 + threadIdx.x;
    const int gs = gridDim.x * 256;
    for (int t = g0; t < 1024; t += gs) {
        int which = t >> 9, i = (t >> 6) & 7, d = t & 63;
        const float* rr = r[which * 8 + i];
        float s = 0.f;
        for (int u = 0; u < 64; u++) s += rr[d + u];
        (which ? g_Tk[dir] : g_Tq[dir])[i * 64 + d] = s;
    }
    for (int t = g0; t < 4608; t += gs) {
        int which = t / 2304, rem = t % 2304, p = rem >> 6, d = rem & 63;
        const float* a = r[which * 8 + c_pi[p]];
        const float* b = r[which * 8 + c_pj[p]];
        float s = 0.f;
        for (int u = 0; u < 64; u++) s = fmaf(a[d + u], b[d + u], s);
        (which ? g_Sk[dir] : g_Sq[dir])[p * 64 + d] = s;
    }
}

// ---------------------------------------------------------------------------
// att_stats: BN statistics of qr/kr/dots without materializing logits.
// ---------------------------------------------------------------------------
__global__ void __launch_bounds__(256) att_stats(int stoff, int dir) {
    const int bw = blockIdx.x, tid = threadIdx.x;
    __shared__ float qT[8][512];   // [h][d*8 + i]
    __shared__ float kT[8][512];
    __shared__ float rsq[8][8], rsk[8][8], tqs[8][8], tks[8][8];

    for (int t = tid; t < 8192; t += 256) {
        int which = t >> 12, o = (t >> 6) & 63, d = t & 63;
        float v = g_qkv[(which * 64 + o) * NT + bw * 64 + d];
        int h = o & 7, i = o >> 3;
        if (which == 0) qT[h][d * 8 + i] = v; else kT[h][d * 8 + i] = v;
    }
    __syncthreads();

    const int h = tid >> 5, lane = tid & 31;
    const float* Tq = g_Tq[dir];
    const float* Tk = g_Tk[dir];
    const float* Sq = g_Sq[dir];
    const float* Sk = g_Sk[dir];
    if (lane < 8) {
        float s = 0.f;
        for (int d = 0; d < 64; d++) s += qT[h][d * 8 + lane];
        rsq[h][lane] = s;
    } else if (lane < 16) {
        int i = lane - 8; float s = 0.f;
        for (int d = 0; d < 64; d++) s += kT[h][d * 8 + i];
        rsk[h][i] = s;
    } else if (lane < 24) {
        int i = lane - 16; float s = 0.f;
        for (int d = 0; d < 64; d++) s = fmaf(qT[h][d * 8 + i], __ldg(&Tq[i * 64 + d]), s);
        tqs[h][i] = s;
    } else {
        int i = lane - 24; float s = 0.f;
        for (int d = 0; d < 64; d++) s = fmaf(kT[h][d * 8 + i], __ldg(&Tk[i * 64 + d]), s);
        tks[h][i] = s;
    }

    float dsq = 0.f, wq = 0.f, wk = 0.f;
    for (int p = lane; p < 36; p += 32) {
        int i = c_pi[p], i2 = c_pj[p];
        float m = (i == i2) ? 1.f : 2.f;
        float gq = 0.f, wqp = 0.f, gk = 0.f, wkp = 0.f;
        for (int d = 0; d < 64; d++) {
            float pq = qT[h][d * 8 + i] * qT[h][d * 8 + i2];
            gq += pq; wqp = fmaf(pq, __ldg(&Sq[p * 64 + d]), wqp);
            float pk = kT[h][d * 8 + i] * kT[h][d * 8 + i2];
            gk += pk; wkp = fmaf(pk, __ldg(&Sk[p * 64 + d]), wkp);
        }
        dsq = fmaf(m * gq, gk, dsq); wq = fmaf(m, wqp, wq); wk = fmaf(m, wkp, wk);
    }
#pragma unroll
    for (int off = 16; off; off >>= 1) {
        dsq += __shfl_xor_sync(~0u, dsq, off);
        wq  += __shfl_xor_sync(~0u, wq,  off);
        wk  += __shfl_xor_sync(~0u, wk,  off);
    }
    __syncwarp();
    if (lane == 0) {
        float ds = 0.f, qs = 0.f, ks = 0.f;
#pragma unroll
        for (int i = 0; i < 8; i++) {
            ds = fmaf(rsq[h][i], rsk[h][i], ds);
            qs += tqs[h][i]; ks += tks[h][i];
        }
        atomicAdd(&g_st[stoff + h * 3 + 0], (double)qs);
        atomicAdd(&g_st[stoff + h * 3 + 1], (double)ks);
        atomicAdd(&g_st[stoff + h * 3 + 2], (double)ds);
        atomicAdd(&g_st[stoff + 24 + h * 3 + 0], (double)wq);
        atomicAdd(&g_st[stoff + 24 + h * 3 + 1], (double)wk);
        atomicAdd(&g_st[stoff + 24 + h * 3 + 2], (double)dsq);
    }
}

// ---------------------------------------------------------------------------
// att_pass2: logits (BN applied) -> softmax -> sv & sve.  Conflict-free:
// Phase A: warp = 8 d-rows, lane = j (stride-1 rel reads, broadcast q/k).
// Phase B: warp = 2 i-channels, lane = d (stride-1 rel, pitch-65 sat).
// ---------------------------------------------------------------------------
__global__ void __launch_bounds__(256) att_pass2(const float* __restrict__ rel,
                                                 int sba, int sto) {
    const int bw = blockIdx.x, h = blockIdx.y, tid = threadIdx.x;
    const int warp = tid >> 5, lane = tid & 31;
    __shared__ float sq[8][65], sk[8][65], svv[16][65];
    __shared__ float srel[32][129];
    __shared__ float sat[64][65];

#pragma unroll
    for (int r = 0; r < 8; r++) {
        int t = tid + r * 256;
        int o = t >> 6, d = t & 63;
        float v = g_qkv[(o * 8 + h) * NT + bw * 64 + d];
        if (o < 8) sq[o][d] = v;
        else if (o < 16) sk[o - 8][d] = v;
        else svv[o - 16][d] = v;
    }
    for (int t = tid; t < 32 * 127; t += 256) srel[t / 127][t % 127] = rel[t];
    const float s0 = g_sb[sba + h * 3], s1v = g_sb[sba + h * 3 + 1], s2v = g_sb[sba + h * 3 + 2];
    const float bsum = g_sb[sba + 24 + h * 3] + g_sb[sba + 24 + h * 3 + 1]
                     + g_sb[sba + 24 + h * 3 + 2];
    __syncthreads();

    {   // ---- Phase A: logits + softmax.  j0 = lane, j1 = lane + 32. ----
        float kk0[8], kk1[8];
#pragma unroll
        for (int i = 0; i < 8; i++) {
            kk0[i] = sk[i][lane];
            kk1[i] = sk[i][lane + 32];
        }
        const int dbase = warp * 8;
#pragma unroll
        for (int r = 0; r < 8; r++) {
            const int d = dbase + r;
            const int m0 = d - lane + 63;   // in [32,126]; m0-32 in [0,94]
            float qr0 = 0, kr0 = 0, dt0 = 0, qr1 = 0, kr1 = 0, dt1 = 0;
#pragma unroll
            for (int i = 0; i < 8; i++) {
                float qi  = sq[i][d];       // broadcast
                float kdi = sk[i][d];       // broadcast
                float rq0 = srel[i][m0],     rq1 = srel[i][m0 - 32];
                float rk0 = srel[8 + i][m0], rk1 = srel[8 + i][m0 - 32];
                qr0 = fmaf(qi, rq0, qr0);   qr1 = fmaf(qi, rq1, qr1);
                kr0 = fmaf(kdi, rk0, kr0);  kr1 = fmaf(kdi, rk1, kr1);
                dt0 = fmaf(qi, kk0[i], dt0); dt1 = fmaf(qi, kk1[i], dt1);
            }
            float l0 = qr0 * s0 + kr0 * s1v + dt0 * s2v + bsum;
            float l1 = qr1 * s0 + kr1 * s1v + dt1 * s2v + bsum;
            float mx = fmaxf(l0, l1);
#pragma unroll
            for (int off = 16; off; off >>= 1)
                mx = fmaxf(mx, __shfl_xor_sync(~0u, mx, off));
            float e0 = __expf(l0 - mx), e1 = __expf(l1 - mx);
            float se = e0 + e1;
#pragma unroll
            for (int off = 16; off; off >>= 1)
                se += __shfl_xor_sync(~0u, se, off);
            float inv = 1.f / se;
            sat[d][lane]      = e0 * inv;
            sat[d][lane + 32] = e1 * inv;
        }
    }
    __syncthreads();

    {   // ---- Phase B: sv & sve.  i0 = 2*warp, i1 = i0+1; da = lane, db = lane+32.
        const int i0 = warp * 2, i1 = i0 + 1;
        const int da = lane, db = lane + 32;
        float av0a = 0, av0b = 0, av1a = 0, av1b = 0;
        float ae0a = 0, ae0b = 0, ae1a = 0, ae1b = 0;
        const float* r0 = &srel[16 + i0][0];
        const float* r1 = &srel[16 + i1][0];
#pragma unroll 4
        for (int j = 0; j < 64; j++) {
            float Aa = sat[da][j];          // stride 65 across lanes: cf
            float Ab = sat[db][j];
            float v0 = svv[i0][j], v1 = svv[i1][j];   // broadcast
            float r0a = r0[da - j + 63], r0b = r0[db - j + 63];
            float r1a = r1[da - j + 63], r1b = r1[db - j + 63];
            av0a = fmaf(Aa, v0, av0a);  av0b = fmaf(Ab, v0, av0b);
            av1a = fmaf(Aa, v1, av1a);  av1b = fmaf(Ab, v1, av1b);
            ae0a = fmaf(Aa, r0a, ae0a); ae0b = fmaf(Ab, r0b, ae0b);
            ae1a = fmaf(Aa, r1a, ae1a); ae1b = fmaf(Ab, r1b, ae1b);
        }
        const int ch0 = h * 16 + i0, ch1 = h * 16 + i1;
        g_outatt[ch0 * NT + bw * 64 + da] = ae0a;
        g_outatt[ch0 * NT + bw * 64 + db] = ae0b;
        g_outatt[ch1 * NT + bw * 64 + da] = ae1a;
        g_outatt[ch1 * NT + bw * 64 + db] = ae1b;
        g_outatt[(128 + ch0) * NT + bw * 64 + da] = av0a;
        g_outatt[(128 + ch0) * NT + bw * 64 + db] = av0b;
        g_outatt[(128 + ch1) * NT + bw * 64 + da] = av1a;
        g_outatt[(128 + ch1) * NT + bw * 64 + db] = av1b;

        float se0 = ae0a + ae0b, qe0 = ae0a * ae0a + ae0b * ae0b;
        float se1 = ae1a + ae1b, qe1 = ae1a * ae1a + ae1b * ae1b;
        float sv0 = av0a + av0b, qv0 = av0a * av0a + av0b * av0b;
        float sv1 = av1a + av1b, qv1 = av1a * av1a + av1b * av1b;
#pragma unroll
        for (int off = 16; off; off >>= 1) {
            se0 += __shfl_xor_sync(~0u, se0, off); qe0 += __shfl_xor_sync(~0u, qe0, off);
            se1 += __shfl_xor_sync(~0u, se1, off); qe1 += __shfl_xor_sync(~0u, qe1, off);
            sv0 += __shfl_xor_sync(~0u, sv0, off); qv0 += __shfl_xor_sync(~0u, qv0, off);
            sv1 += __shfl_xor_sync(~0u, sv1, off); qv1 += __shfl_xor_sync(~0u, qv1, off);
        }
        if (lane == 0) {
            atomicAdd(&g_st[sto + ch0], (double)se0);
            atomicAdd(&g_st[sto + ch1], (double)se1);
            atomicAdd(&g_st[sto + 256 + ch0], (double)qe0);
            atomicAdd(&g_st[sto + 256 + ch1], (double)qe1);
            atomicAdd(&g_st[sto + 128 + ch0], (double)sv0);
            atomicAdd(&g_st[sto + 128 + ch1], (double)sv1);
            atomicAdd(&g_st[sto + 256 + 128 + ch0], (double)qv0);
            atomicAdd(&g_st[sto + 256 + 128 + ch1], (double)qv1);
        }
    }
}

// combine att1: x3[c][b][h][w] = bn(sve) + bn(sv), with h<->w transpose
__global__ void __launch_bounds__(256) combine1() {
    const int c = blockIdx.x, b = blockIdx.y, tid = threadIdx.x;
    __shared__ float tile[64][65];
    const float sA = g_sb[304 + c],        bA = g_sb[304 + 256 + c];
    const float sB = g_sb[304 + c + 128],  bB = g_sb[304 + 256 + c + 128];
    const float* pA = g_outatt + c * NT + b * 4096;
    const float* pB = g_outatt + (c + 128) * NT + b * 4096;
    for (int t = tid; t < 4096; t += 256)
        tile[t >> 6][t & 63] = pA[t] * sA + bA + pB[t] * sB + bB;
    __syncthreads();
    float* q = g_x3 + c * NT + b * 4096;
    for (int t = tid; t < 4096; t += 256)
        q[t] = tile[t & 63][t >> 6];
}

// final: out = relu(bn(conv_out) + x_in)
__global__ void __launch_bounds__(256) final_k(const float* __restrict__ x_in,
                                               float* __restrict__ out) {
    int idx = blockIdx.x * 256 + threadIdx.x;
    int o = idx >> 15, m = idx & (NT - 1);
    int b = m >> 12, hw = m & 4095;
    float v = g_y2[idx] * g_sb[1376 + o] + g_sb[1376 + 256 + o];
    int oidx = (b * 256 + o) * 4096 + hw;
    v += x_in[oidx];
    out[oidx] = fmaxf(v, 0.f);
}

// ---------------------------------------------------------------------------
extern "C" void kernel_launch(void* const* d_in, const int* in_sizes, int n_in,
                              void* d_out, int out_size) {
    (void)in_sizes; (void)n_in; (void)out_size;
    const float* x_in   = (const float*)d_in[0];
    const float* w_in   = (const float*)d_in[1];
    const float* g_in   = (const float*)d_in[2];
    const float* b_in   = (const float*)d_in[3];
    const float* w_out  = (const float*)d_in[4];
    const float* g_out  = (const float*)d_in[5];
    const float* b_out  = (const float*)d_in[6];
    const float* wqkv_h = (const float*)d_in[7];
    const float* rel_h  = (const float*)d_in[8];
    const float* ga_h   = (const float*)d_in[9];
    const float* ba_h   = (const float*)d_in[10];
    const float* go_h   = (const float*)d_in[11];
    const float* bo_h   = (const float*)d_in[12];
    const float* wqkv_w = (const float*)d_in[13];
    const float* rel_w  = (const float*)d_in[14];
    const float* ga_w   = (const float*)d_in[15];
    const float* ba_w   = (const float*)d_in[16];
    const float* go_w   = (const float*)d_in[17];
    const float* bo_w   = (const float*)d_in[18];

    zero_stats<<<8, 256>>>();                                   // 0
    prep_S<<<23, 256>>>(rel_h, 0);                              // 1
    prep_S<<<23, 256>>>(rel_w, 1);                              // 2

    // conv-in (+stats) -> y1                                   // 3 (profiled)
    gemm_k<0><<<dim3(256, 1), 256>>>(w_in, x_in, 256);
    make_scale<<<2, 64>>>(0, g_in, b_in, 0, 128, 1.f / 32768.f);

    // --- axial attention along H ---
    gemm_k<1><<<dim3(256, 2), 256>>>(wqkv_h, nullptr, 128);
    att_stats<<<512, 256>>>(256, 0);
    make_scale<<<1, 64>>>(256, ga_h, ba_h, 256, 24, 1.f / 2097152.f);
    att_pass2<<<dim3(512, 8), 256>>>(rel_h, 256, 304);
    make_scale<<<4, 64>>>(304, go_h, bo_h, 304, 256, 1.f / 32768.f);
    combine1<<<dim3(128, 8), 256>>>();

    // --- axial attention along W ---
    gemm_k<2><<<dim3(256, 2), 256>>>(wqkv_w, nullptr, 128);
    att_stats<<<512, 256>>>(816, 1);
    make_scale<<<1, 64>>>(816, ga_w, ba_w, 816, 24, 1.f / 2097152.f);
    att_pass2<<<dim3(512, 8), 256>>>(rel_w, 816, 864);
    make_scale<<<4, 64>>>(864, go_w, bo_w, 864, 256, 1.f / 32768.f);

    // conv-out (combine2 fused in prologue, +stats) -> y2
    gemm_k<3><<<dim3(256, 2), 256>>>(w_out, nullptr, 128);
    make_scale<<<4, 64>>>(1376, g_out, b_out, 1376, 256, 1.f / 32768.f);

    final_k<<<32768, 256>>>(x_in, (float*)d_out);
}